// round 1
// baseline (speedup 1.0000x reference)
#include <cuda_runtime.h>
#include <math.h>

// ---------------------------------------------------------------------------
// RWKV v6 TimeMix  (B=4, T=1024, C=1024, H=16, K=64)
// Round 1: correctness-first fp32 implementation.
//   - classic 128x128x8 SGEMM (8x8 thread tiles) with fused epilogues
//   - WKV6 sequential scan: 1 block per (b,h), 64 threads, state in registers
//   - fused groupnorm + gate
// ---------------------------------------------------------------------------

#define Bc 4
#define Tc 1024
#define Cc 1024
#define Hh 16
#define Kk 64
#define MT (Bc * Tc)          // 4096 rows
#define EPSC (1e-5f * 64.0f)  // 1e-5 * HEAD_SIZE_DIVISOR^2

// ------------------------- scratch (static device mem) ---------------------
__device__ float g_xx [MT * Cc];
__device__ float g_xxx[MT * Cc];
__device__ float g_m  [MT * 160];
__device__ float g_xw [MT * Cc];
__device__ float g_xk [MT * Cc];
__device__ float g_xv [MT * Cc];
__device__ float g_xr [MT * Cc];
__device__ float g_xg [MT * Cc];
__device__ float g_r  [MT * Cc];
__device__ float g_k  [MT * Cc];
__device__ float g_v  [MT * Cc];
__device__ float g_g  [MT * Cc];
__device__ float g_w  [MT * Cc];
__device__ float g_t64[MT * 64];
__device__ float g_y  [MT * Cc];
__device__ float g_z  [MT * Cc];

// ------------------------- elementwise: token shift ------------------------
__global__ void shift_kernel(const float* __restrict__ x,
                             const float* __restrict__ maa_x,
                             float* __restrict__ xx,
                             float* __restrict__ xxx)
{
    int i = blockIdx.x * blockDim.x + threadIdx.x;
    if (i >= MT * Cc) return;
    int c = i & (Cc - 1);
    int t = (i >> 10) & (Tc - 1);
    float xv = x[i];
    float xp = (t != 0) ? x[i - Cc] : 0.0f;
    float d  = xp - xv;
    xx[i]  = d;
    xxx[i] = xv + d * maa_x[c];
}

// ------------------------- generic tiled SGEMM -----------------------------
// C[M,N] = epi(A[M,K] @ B[K,N])
enum { EPI_NONE = 0, EPI_TANH = 1, EPI_SILU = 2, EPI_BIAS = 3, EPI_MIX = 4 };

template <int EPI>
__global__ __launch_bounds__(256)
void sgemm_kernel(const float* __restrict__ A, const float* __restrict__ B,
                  float* __restrict__ Cm, int M, int N, int K,
                  int lda, int ldb, int ldc,
                  const float* __restrict__ bias,
                  const float* __restrict__ ex,
                  const float* __restrict__ exx)
{
    __shared__ float As[8][128];
    __shared__ float Bs[8][128];

    const int tid = threadIdx.x;
    const int m0  = blockIdx.y * 128;
    const int n0  = blockIdx.x * 128;
    const int ty  = tid >> 4;       // 0..15
    const int tx  = tid & 15;       // 0..15

    float acc[8][8];
#pragma unroll
    for (int i = 0; i < 8; i++)
#pragma unroll
        for (int j = 0; j < 8; j++) acc[i][j] = 0.0f;

    // A tile load mapping: 128 rows x 8 cols, float4 per thread
    const int arow = tid >> 1;          // 0..127
    const int acol = (tid & 1) * 4;     // 0 or 4
    // B tile load mapping: 8 rows x 128 cols, float4 per thread
    const int brow = tid >> 5;          // 0..7
    const int bcol = (tid & 31) * 4;    // 0..124

    const float* Aptr = A + (size_t)(m0 + arow) * lda + acol;
    const float* Bptr = B + (size_t)brow * ldb + n0 + bcol;
    const bool   bvalid = (n0 + bcol) < N;

    for (int k0 = 0; k0 < K; k0 += 8) {
        float4 av = *reinterpret_cast<const float4*>(Aptr + k0);
        float4 bv = bvalid
            ? *reinterpret_cast<const float4*>(Bptr + (size_t)k0 * ldb)
            : make_float4(0.f, 0.f, 0.f, 0.f);

        As[acol + 0][arow] = av.x;
        As[acol + 1][arow] = av.y;
        As[acol + 2][arow] = av.z;
        As[acol + 3][arow] = av.w;
        *reinterpret_cast<float4*>(&Bs[brow][bcol]) = bv;
        __syncthreads();

#pragma unroll
        for (int kk = 0; kk < 8; kk++) {
            float a[8], b[8];
#pragma unroll
            for (int i = 0; i < 8; i++) a[i] = As[kk][ty * 8 + i];
#pragma unroll
            for (int j = 0; j < 8; j++) b[j] = Bs[kk][tx * 8 + j];
#pragma unroll
            for (int i = 0; i < 8; i++)
#pragma unroll
                for (int j = 0; j < 8; j++)
                    acc[i][j] = fmaf(a[i], b[j], acc[i][j]);
        }
        __syncthreads();
    }

#pragma unroll
    for (int i = 0; i < 8; i++) {
        const int row = m0 + ty * 8 + i;
#pragma unroll
        for (int j = 0; j < 8; j++) {
            const int col = n0 + tx * 8 + j;
            if (col < N) {
                float v = acc[i][j];
                size_t idx = (size_t)row * ldc + col;
                if (EPI == EPI_TANH)      v = tanhf(v);
                else if (EPI == EPI_SILU) v = v / (1.0f + expf(-v));
                else if (EPI == EPI_BIAS) v = v + bias[col];
                else if (EPI == EPI_MIX)  v = ex[idx] + exx[idx] * (bias[col] + v);
                Cm[idx] = v;
            }
        }
    }
}

// ------------------------- WKV6 sequential scan ----------------------------
// grid: B*H blocks, 64 threads; thread j owns state column S[:, j]
__global__ __launch_bounds__(64)
void wkv6_kernel(const float* __restrict__ r, const float* __restrict__ k,
                 const float* __restrict__ v, const float* __restrict__ w,
                 const float* __restrict__ u, float* __restrict__ y)
{
    const int bh = blockIdx.x;
    const int b  = bh >> 4;
    const int h  = bh & 15;
    const int j  = threadIdx.x;

    const size_t base = (size_t)b * Tc * Cc + h * Kk + j;
    const float  uj   = u[h * Kk + j];

    float S[64];
#pragma unroll
    for (int i = 0; i < 64; i++) S[i] = 0.0f;

    __shared__ float4 q[64];  // {r, k, wdec, u} per key index

    for (int t = 0; t < Tc; t++) {
        const size_t off = base + (size_t)t * Cc;
        float rj = r[off];
        float kj = k[off];
        float wj = w[off];
        float vj = v[off];
        float wd = expf(-expf(wj));
        q[j] = make_float4(rj, kj, wd, uj);
        __syncthreads();

        float y0 = 0.f, y1 = 0.f, y2 = 0.f, y3 = 0.f;
#pragma unroll
        for (int kk = 0; kk < 64; kk += 4) {
            float4 q0 = q[kk + 0];
            float4 q1 = q[kk + 1];
            float4 q2 = q[kk + 2];
            float4 q3 = q[kk + 3];
            float kv0 = q0.y * vj;
            float kv1 = q1.y * vj;
            float kv2 = q2.y * vj;
            float kv3 = q3.y * vj;
            y0 = fmaf(q0.x, fmaf(q0.w, kv0, S[kk + 0]), y0);
            y1 = fmaf(q1.x, fmaf(q1.w, kv1, S[kk + 1]), y1);
            y2 = fmaf(q2.x, fmaf(q2.w, kv2, S[kk + 2]), y2);
            y3 = fmaf(q3.x, fmaf(q3.w, kv3, S[kk + 3]), y3);
            S[kk + 0] = fmaf(S[kk + 0], q0.z, kv0);
            S[kk + 1] = fmaf(S[kk + 1], q1.z, kv1);
            S[kk + 2] = fmaf(S[kk + 2], q2.z, kv2);
            S[kk + 3] = fmaf(S[kk + 3], q3.z, kv3);
        }
        y[off] = (y0 + y1) + (y2 + y3);
        __syncthreads();
    }
}

// ------------------------- groupnorm + gate --------------------------------
// grid: MT blocks, 256 threads; each thread handles 4 channels
// head h = channels [64h, 64h+64) = 16 consecutive threads (aligned to 16-lane groups)
__global__ __launch_bounds__(256)
void gnorm_kernel(const float* __restrict__ y, const float* __restrict__ gate,
                  const float* __restrict__ gamma, const float* __restrict__ beta,
                  float* __restrict__ z)
{
    const int row = blockIdx.x;
    const int tid = threadIdx.x;
    const int c0  = tid * 4;
    const size_t idx = (size_t)row * Cc + c0;

    float4 yv = *reinterpret_cast<const float4*>(y + idx);
    float s  = yv.x + yv.y + yv.z + yv.w;
    float ss = yv.x * yv.x + yv.y * yv.y + yv.z * yv.z + yv.w * yv.w;
#pragma unroll
    for (int o = 8; o > 0; o >>= 1) {
        s  += __shfl_xor_sync(0xffffffffu, s,  o);
        ss += __shfl_xor_sync(0xffffffffu, ss, o);
    }
    const float mean = s * (1.0f / 64.0f);
    const float var  = ss * (1.0f / 64.0f) - mean * mean;
    const float rstd = rsqrtf(var + EPSC);

    float4 gm = *reinterpret_cast<const float4*>(gamma + c0);
    float4 bt = *reinterpret_cast<const float4*>(beta + c0);
    float4 gt = *reinterpret_cast<const float4*>(gate + idx);
    float4 o;
    o.x = ((yv.x - mean) * rstd * gm.x + bt.x) * gt.x;
    o.y = ((yv.y - mean) * rstd * gm.y + bt.y) * gt.y;
    o.z = ((yv.z - mean) * rstd * gm.z + bt.z) * gt.z;
    o.w = ((yv.w - mean) * rstd * gm.w + bt.w) * gt.w;
    *reinterpret_cast<float4*>(z + idx) = o;
}

// ---------------------------------------------------------------------------
extern "C" void kernel_launch(void* const* d_in, const int* in_sizes, int n_in,
                              void* d_out, int out_size)
{
    const float* x      = (const float*)d_in[0];
    const float* maa_x  = (const float*)d_in[1];
    const float* maa_w  = (const float*)d_in[2];
    const float* maa_k  = (const float*)d_in[3];
    const float* maa_v  = (const float*)d_in[4];
    const float* maa_r  = (const float*)d_in[5];
    const float* maa_g  = (const float*)d_in[6];
    const float* maa_w1 = (const float*)d_in[7];   // (C,160)
    const float* maa_w2 = (const float*)d_in[8];   // (5,32,C)
    const float* tdecay = (const float*)d_in[9];   // (C)
    const float* dw1    = (const float*)d_in[10];  // (C,64)
    const float* dw2    = (const float*)d_in[11];  // (64,C)
    const float* u      = (const float*)d_in[12];  // (H,K)
    const float* W_r    = (const float*)d_in[13];
    const float* W_k    = (const float*)d_in[14];
    const float* W_v    = (const float*)d_in[15];
    const float* W_g    = (const float*)d_in[16];
    const float* W_o    = (const float*)d_in[17];
    const float* gamma  = (const float*)d_in[18];
    const float* beta   = (const float*)d_in[19];
    float* out = (float*)d_out;

    float *xx, *xxx, *m, *xw, *xk, *xv, *xr, *xg;
    float *rr, *kk, *vv, *gg, *ww, *t64, *y, *z;
    cudaGetSymbolAddress((void**)&xx,  g_xx);
    cudaGetSymbolAddress((void**)&xxx, g_xxx);
    cudaGetSymbolAddress((void**)&m,   g_m);
    cudaGetSymbolAddress((void**)&xw,  g_xw);
    cudaGetSymbolAddress((void**)&xk,  g_xk);
    cudaGetSymbolAddress((void**)&xv,  g_xv);
    cudaGetSymbolAddress((void**)&xr,  g_xr);
    cudaGetSymbolAddress((void**)&xg,  g_xg);
    cudaGetSymbolAddress((void**)&rr,  g_r);
    cudaGetSymbolAddress((void**)&kk,  g_k);
    cudaGetSymbolAddress((void**)&vv,  g_v);
    cudaGetSymbolAddress((void**)&gg,  g_g);
    cudaGetSymbolAddress((void**)&ww,  g_w);
    cudaGetSymbolAddress((void**)&t64, g_t64);
    cudaGetSymbolAddress((void**)&y,   g_y);
    cudaGetSymbolAddress((void**)&z,   g_z);

    // 1) token shift + xxx
    shift_kernel<<<(MT * Cc + 255) / 256, 256>>>(x, maa_x, xx, xxx);

    auto grd = [](int N, int M) { return dim3((N + 127) / 128, (M + 127) / 128); };

    // 2) m = tanh(xxx @ W1)   [4096 x 160 x 1024]
    sgemm_kernel<EPI_TANH><<<grd(160, MT), 256>>>(
        xxx, maa_w1, m, MT, 160, 1024, 1024, 160, 160, nullptr, nullptr, nullptr);

    // 3) five mixing GEMMs: x* = x + xx*(maa_* + m_f @ W2_f)   [4096 x 1024 x 32]
    const float* bias5[5] = {maa_w, maa_k, maa_v, maa_r, maa_g};
    float*       out5[5]  = {xw, xk, xv, xr, xg};
    for (int f = 0; f < 5; f++) {
        sgemm_kernel<EPI_MIX><<<grd(1024, MT), 256>>>(
            m + f * 32, maa_w2 + (size_t)f * 32 * 1024, out5[f],
            MT, 1024, 32, 160, 1024, 1024, bias5[f], x, xx);
    }

    // 4) big projections [4096 x 1024 x 1024]
    sgemm_kernel<EPI_NONE><<<grd(1024, MT), 256>>>(
        xr, W_r, rr, MT, 1024, 1024, 1024, 1024, 1024, nullptr, nullptr, nullptr);
    sgemm_kernel<EPI_NONE><<<grd(1024, MT), 256>>>(
        xk, W_k, kk, MT, 1024, 1024, 1024, 1024, 1024, nullptr, nullptr, nullptr);
    sgemm_kernel<EPI_NONE><<<grd(1024, MT), 256>>>(
        xv, W_v, vv, MT, 1024, 1024, 1024, 1024, 1024, nullptr, nullptr, nullptr);
    sgemm_kernel<EPI_SILU><<<grd(1024, MT), 256>>>(
        xg, W_g, gg, MT, 1024, 1024, 1024, 1024, 1024, nullptr, nullptr, nullptr);

    // 5) decay LoRA: w = time_decay + tanh(xw @ dw1) @ dw2
    sgemm_kernel<EPI_TANH><<<grd(64, MT), 256>>>(
        xw, dw1, t64, MT, 64, 1024, 1024, 64, 64, nullptr, nullptr, nullptr);
    sgemm_kernel<EPI_BIAS><<<grd(1024, MT), 256>>>(
        t64, dw2, ww, MT, 1024, 64, 64, 1024, 1024, tdecay, nullptr, nullptr);

    // 6) WKV6 scan
    wkv6_kernel<<<Bc * Hh, 64>>>(rr, kk, vv, ww, u, y);

    // 7) groupnorm + gate
    gnorm_kernel<<<MT, 256>>>(y, gg, gamma, beta, z);

    // 8) output projection
    sgemm_kernel<EPI_NONE><<<grd(1024, MT), 256>>>(
        z, W_o, out, MT, 1024, 1024, 1024, 1024, 1024, nullptr, nullptr, nullptr);
}

// round 8
// speedup vs baseline: 1.2552x; 1.2552x over previous
#include <cuda_runtime.h>
#include <math.h>
#include <stdint.h>

// ---------------------------------------------------------------------------
// RWKV v6 TimeMix  (B=4, T=1024, C=1024, H=16, K=64)
// Round 8: 3xTF32 error-compensated mma.sync GEMMs (hi/lo decomposition,
// D = Ahi*Bhi + Ahi*Blo + Alo*Bhi) + cp.async 4-stage pipeline.
// R7 failed at rel_err 1.03e-3 (amplified tf32 truncation via decay path).
// ---------------------------------------------------------------------------

#define Bc 4
#define Tc 1024
#define Cc 1024
#define Hh 16
#define Kk 64
#define MT (Bc * Tc)          // 4096 rows
#define EPSC (1e-5f * 64.0f)

// ------------------------- scratch (static device mem) ---------------------
__device__ float g_xx  [MT * Cc];
__device__ float g_xxx [MT * Cc];
__device__ float g_m   [MT * 160];
__device__ float g_xw  [MT * Cc];
__device__ float g_xk  [MT * Cc];
__device__ float g_xv  [MT * Cc];
__device__ float g_xr  [MT * Cc];
__device__ float g_xg  [MT * Cc];
__device__ float g_r   [MT * Cc];
__device__ float g_k   [MT * Cc];
__device__ float g_v   [MT * Cc];
__device__ float g_g   [MT * Cc];
__device__ float g_w   [MT * Cc];
__device__ float g_t64 [MT * 64];
__device__ float g_y   [MT * Cc];
__device__ float g_z   [MT * Cc];
__device__ float g_wt5 [5 * Cc * Cc];   // W_r/k/v/g/o transposed [N][K], full fp32
__device__ float g_w1t [160 * Cc];      // maa_w1^T  [160][1024]
__device__ float g_w2t [5 * Cc * 32];   // per-f w2^T [1024][32]
__device__ float g_dw1t[64 * Cc];       // dw1^T [64][1024]
__device__ float g_dw2t[Cc * 64];       // dw2^T [1024][64]

// ======================= 3xTF32 mma.sync GEMM ==============================
// D[M,N] = epi(A[M,K] @ B[N,K]^T), A row-major, B stored [N][K] (".col").
// BM=128 BN=128 BK=32, 256 threads (8 warps, 2x4 of 64x32 warp tiles),
// 4-stage cp.async pipeline. Batched over grid.z with per-z N/ldc/epi.
enum { EPI_NONE = 0, EPI_TANH = 1, EPI_SILU = 2, EPI_BIAS = 3, EPI_MIX = 4 };

struct GemmBatch {
    const float* A[5];
    const float* B[5];
    float*       C[5];
    const float* bias[5];
    int          N[5];
    int          ldc[5];
    int          epi[5];
    const float* ex;      // x   (EPI_MIX)
    const float* exx;     // xx  (EPI_MIX)
    int K, lda, ldb;
};

#define GSTAGE_FLOATS 9216            // (128*36)*2 per stage
#define GSTAGE_BYTES  36864u
#define GSMEM_BYTES   (4u * GSTAGE_BYTES)   // 147456

__device__ __forceinline__ void cp16(uint32_t saddr, const void* gptr, int sz) {
    asm volatile("cp.async.cg.shared.global [%0], [%1], 16, %2;"
                 :: "r"(saddr), "l"(gptr), "r"(sz));
}
__device__ __forceinline__ void cp_commit() {
    asm volatile("cp.async.commit_group;" ::: "memory");
}
__device__ __forceinline__ void cp_wait2() {
    asm volatile("cp.async.wait_group 2;" ::: "memory");
}
__device__ __forceinline__ uint32_t smem_u32(const void* p) {
    uint32_t a;
    asm("{ .reg .u64 t; cvta.to.shared.u64 t, %1; cvt.u32.u64 %0, t; }"
        : "=r"(a) : "l"(p));
    return a;
}
// hi/lo tf32 decomposition: v = hi + lo (to ~fp32 precision)
__device__ __forceinline__ void split_tf32(float v, uint32_t& hi, uint32_t& lo) {
    asm("cvt.rna.tf32.f32 %0, %1;" : "=r"(hi) : "f"(v));
    float d = v - __uint_as_float(hi);
    asm("cvt.rna.tf32.f32 %0, %1;" : "=r"(lo) : "f"(d));
}
__device__ __forceinline__ void mma_tf32_16n8k8(float c[4],
    uint32_t a0, uint32_t a1, uint32_t a2, uint32_t a3, uint32_t b0, uint32_t b1)
{
    asm volatile(
        "mma.sync.aligned.m16n8k8.row.col.f32.tf32.tf32.f32 "
        "{%0,%1,%2,%3}, {%4,%5,%6,%7}, {%8,%9}, {%0,%1,%2,%3};"
        : "+f"(c[0]), "+f"(c[1]), "+f"(c[2]), "+f"(c[3])
        : "r"(a0), "r"(a1), "r"(a2), "r"(a3), "r"(b0), "r"(b1));
}

__global__ void __launch_bounds__(256, 1)
gemm_mma_kernel(const GemmBatch args)
{
    extern __shared__ float smem[];
    const int z  = blockIdx.z;
    const int Nz = args.N[z];
    const int n0 = blockIdx.x * 128;
    if (n0 >= Nz) return;
    const int m0 = blockIdx.y * 128;

    const int tid = threadIdx.x;
    const int wid = tid >> 5;
    const int lid = tid & 31;
    const int wm  = wid >> 2;          // 0..1
    const int wn  = wid & 3;           // 0..3
    const int gid = lid >> 2;          // 0..7
    const int tig = lid & 3;           // 0..3

    const float* Ag = args.A[z];
    const float* Bg = args.B[z];
    const int lda = args.lda, ldb = args.ldb, K = args.K;
    const int NIT = K >> 5;

    // cp.async mapping: 2 threads per row, 64B each
    const int arow = tid >> 1;
    const int acol = (tid & 1) * 16;
    const uint32_t sbase = smem_u32(smem);
    const int brow_ok = (n0 + arow) < Nz;
    const int bsz = brow_ok ? 16 : 0;
    const float* gArow = Ag + (size_t)(m0 + arow) * lda + acol;
    const float* gBrow = Bg + (size_t)(brow_ok ? (n0 + arow) : 0) * ldb + acol;

    auto load_stage = [&](int stage, int kt) {
        const uint32_t sA = sbase + (uint32_t)stage * GSTAGE_BYTES
                          + (uint32_t)(arow * 36 + acol) * 4u;
        const uint32_t sB = sA + 18432u;
        const float* ga = gArow + kt * 32;
        const float* gb = gBrow + kt * 32;
#pragma unroll
        for (int i = 0; i < 4; i++) cp16(sA + i * 16u, ga + i * 4, 16);
#pragma unroll
        for (int i = 0; i < 4; i++) cp16(sB + i * 16u, gb + i * 4, bsz);
    };

    float c[4][4][4];
#pragma unroll
    for (int mt = 0; mt < 4; mt++)
#pragma unroll
        for (int nt = 0; nt < 4; nt++)
#pragma unroll
            for (int i = 0; i < 4; i++) c[mt][nt][i] = 0.0f;

    // prologue: always commit 3 groups (empty if NIT small)
#pragma unroll
    for (int p = 0; p < 3; p++) {
        if (p < NIT) load_stage(p, p);
        cp_commit();
    }

    for (int kt = 0; kt < NIT; kt++) {
        cp_wait2();
        __syncthreads();

        const float* As  = smem + (kt & 3) * GSTAGE_FLOATS;
        const float* Bs  = As + 4608;
        const int    am  = wm * 64 + gid;
        const int    bn  = wn * 32 + gid;

#pragma unroll
        for (int ks = 0; ks < 4; ks++) {
            const int k0 = ks * 8 + tig;
            uint32_t bh[4][2], bl[4][2];
#pragma unroll
            for (int nt = 0; nt < 4; nt++) {
                const float* bp = Bs + (bn + nt * 8) * 36 + k0;
                split_tf32(bp[0], bh[nt][0], bl[nt][0]);
                split_tf32(bp[4], bh[nt][1], bl[nt][1]);
            }
#pragma unroll
            for (int mt = 0; mt < 4; mt++) {
                const float* ap = As + (am + mt * 16) * 36 + k0;
                uint32_t ah[4], al[4];
                split_tf32(ap[0],          ah[0], al[0]);
                split_tf32(ap[8 * 36],     ah[1], al[1]);
                split_tf32(ap[4],          ah[2], al[2]);
                split_tf32(ap[8 * 36 + 4], ah[3], al[3]);
#pragma unroll
                for (int nt = 0; nt < 4; nt++) {
                    mma_tf32_16n8k8(c[mt][nt], ah[0], ah[1], ah[2], ah[3],
                                    bh[nt][0], bh[nt][1]);
                    mma_tf32_16n8k8(c[mt][nt], ah[0], ah[1], ah[2], ah[3],
                                    bl[nt][0], bl[nt][1]);
                    mma_tf32_16n8k8(c[mt][nt], al[0], al[1], al[2], al[3],
                                    bh[nt][0], bh[nt][1]);
                }
            }
        }
        __syncthreads();
        const int j = kt + 3;
        if (j < NIT) load_stage(j & 3, j);
        cp_commit();
    }

    // -------- epilogue --------
    const int ep = args.epi[z];
    const float* bias = args.bias[z];
    float* Cg = args.C[z];
    const int ldc = args.ldc[z];
    const float* ex  = args.ex;
    const float* exx = args.exx;

    auto apply2 = [&](float& v0, float& v1, int row, int col) {
        if (ep == EPI_TANH) { v0 = tanhf(v0); v1 = tanhf(v1); }
        else if (ep == EPI_SILU) {
            v0 = v0 / (1.0f + expf(-v0));
            v1 = v1 / (1.0f + expf(-v1));
        } else if (ep == EPI_BIAS) { v0 += bias[col]; v1 += bias[col + 1]; }
        else if (ep == EPI_MIX) {
            size_t idx = (size_t)row * 1024 + col;
            float2 e  = *reinterpret_cast<const float2*>(ex  + idx);
            float2 dx = *reinterpret_cast<const float2*>(exx + idx);
            v0 = e.x + dx.x * (bias[col]     + v0);
            v1 = e.y + dx.y * (bias[col + 1] + v1);
        }
    };

#pragma unroll
    for (int mt = 0; mt < 4; mt++) {
        const int r0 = m0 + wm * 64 + mt * 16 + gid;
#pragma unroll
        for (int nt = 0; nt < 4; nt++) {
            const int col = n0 + wn * 32 + nt * 8 + tig * 2;
            if (col < Nz) {
                float v0 = c[mt][nt][0], v1 = c[mt][nt][1];
                apply2(v0, v1, r0, col);
                *reinterpret_cast<float2*>(Cg + (size_t)r0 * ldc + col)
                    = make_float2(v0, v1);
                float v2 = c[mt][nt][2], v3 = c[mt][nt][3];
                apply2(v2, v3, r0 + 8, col);
                *reinterpret_cast<float2*>(Cg + (size_t)(r0 + 8) * ldc + col)
                    = make_float2(v2, v3);
            }
        }
    }
}

// ------------------------- generic fp32 transpose --------------------------
// dst[c][r] = src[r][c];  R, C multiples of 32. Full precision retained
// (hi/lo decomposition happens inside the GEMM).
__global__ void transpose_kernel(const float* __restrict__ src,
                                 float* __restrict__ dst, int R, int C)
{
    __shared__ float tile[32][33];
    const int bx = blockIdx.x * 32, by = blockIdx.y * 32;
    const int tx = threadIdx.x, ty = threadIdx.y;   // (32, 8)
#pragma unroll
    for (int r = 0; r < 32; r += 8)
        tile[ty + r][tx] = src[(size_t)(by + ty + r) * C + bx + tx];
    __syncthreads();
#pragma unroll
    for (int r = 0; r < 32; r += 8)
        dst[(size_t)(bx + ty + r) * R + by + tx] = tile[tx][ty + r];
}

// ------------------------- elementwise: token shift ------------------------
__global__ void shift_kernel(const float* __restrict__ x,
                             const float* __restrict__ maa_x,
                             float* __restrict__ xx,
                             float* __restrict__ xxx)
{
    int i = blockIdx.x * blockDim.x + threadIdx.x;
    if (i >= MT * Cc) return;
    int c = i & (Cc - 1);
    int t = (i >> 10) & (Tc - 1);
    float xv = x[i];
    float xp = (t != 0) ? x[i - Cc] : 0.0f;
    float d  = xp - xv;
    xx[i]  = d;
    xxx[i] = xv + d * maa_x[c];
}

// ------------------------- WKV6 sequential scan ----------------------------
__global__ __launch_bounds__(64)
void wkv6_kernel(const float* __restrict__ r, const float* __restrict__ k,
                 const float* __restrict__ v, const float* __restrict__ w,
                 const float* __restrict__ u, float* __restrict__ y)
{
    const int bh = blockIdx.x;
    const int b  = bh >> 4;
    const int h  = bh & 15;
    const int j  = threadIdx.x;

    const size_t base = (size_t)b * Tc * Cc + h * Kk + j;
    const float  uj   = u[h * Kk + j];

    float S[64];
#pragma unroll
    for (int i = 0; i < 64; i++) S[i] = 0.0f;

    __shared__ float4 q[64];

    for (int t = 0; t < Tc; t++) {
        const size_t off = base + (size_t)t * Cc;
        float rj = r[off];
        float kj = k[off];
        float wj = w[off];
        float vj = v[off];
        float wd = expf(-expf(wj));
        q[j] = make_float4(rj, kj, wd, uj);
        __syncthreads();

        float y0 = 0.f, y1 = 0.f, y2 = 0.f, y3 = 0.f;
#pragma unroll
        for (int kk = 0; kk < 64; kk += 4) {
            float4 q0 = q[kk + 0];
            float4 q1 = q[kk + 1];
            float4 q2 = q[kk + 2];
            float4 q3 = q[kk + 3];
            float kv0 = q0.y * vj;
            float kv1 = q1.y * vj;
            float kv2 = q2.y * vj;
            float kv3 = q3.y * vj;
            y0 = fmaf(q0.x, fmaf(q0.w, kv0, S[kk + 0]), y0);
            y1 = fmaf(q1.x, fmaf(q1.w, kv1, S[kk + 1]), y1);
            y2 = fmaf(q2.x, fmaf(q2.w, kv2, S[kk + 2]), y2);
            y3 = fmaf(q3.x, fmaf(q3.w, kv3, S[kk + 3]), y3);
            S[kk + 0] = fmaf(S[kk + 0], q0.z, kv0);
            S[kk + 1] = fmaf(S[kk + 1], q1.z, kv1);
            S[kk + 2] = fmaf(S[kk + 2], q2.z, kv2);
            S[kk + 3] = fmaf(S[kk + 3], q3.z, kv3);
        }
        y[off] = (y0 + y1) + (y2 + y3);
        __syncthreads();
    }
}

// ------------------------- groupnorm + gate --------------------------------
__global__ __launch_bounds__(256)
void gnorm_kernel(const float* __restrict__ y, const float* __restrict__ gate,
                  const float* __restrict__ gamma, const float* __restrict__ beta,
                  float* __restrict__ z)
{
    const int row = blockIdx.x;
    const int tid = threadIdx.x;
    const int c0  = tid * 4;
    const size_t idx = (size_t)row * Cc + c0;

    float4 yv = *reinterpret_cast<const float4*>(y + idx);
    float s  = yv.x + yv.y + yv.z + yv.w;
    float ss = yv.x * yv.x + yv.y * yv.y + yv.z * yv.z + yv.w * yv.w;
#pragma unroll
    for (int o = 8; o > 0; o >>= 1) {
        s  += __shfl_xor_sync(0xffffffffu, s,  o);
        ss += __shfl_xor_sync(0xffffffffu, ss, o);
    }
    const float mean = s * (1.0f / 64.0f);
    const float var  = ss * (1.0f / 64.0f) - mean * mean;
    const float rstd = rsqrtf(var + EPSC);

    float4 gm = *reinterpret_cast<const float4*>(gamma + c0);
    float4 bt = *reinterpret_cast<const float4*>(beta + c0);
    float4 gt = *reinterpret_cast<const float4*>(gate + idx);
    float4 o;
    o.x = ((yv.x - mean) * rstd * gm.x + bt.x) * gt.x;
    o.y = ((yv.y - mean) * rstd * gm.y + bt.y) * gt.y;
    o.z = ((yv.z - mean) * rstd * gm.z + bt.z) * gt.z;
    o.w = ((yv.w - mean) * rstd * gm.w + bt.w) * gt.w;
    *reinterpret_cast<float4*>(z + idx) = o;
}

// ---------------------------------------------------------------------------
extern "C" void kernel_launch(void* const* d_in, const int* in_sizes, int n_in,
                              void* d_out, int out_size)
{
    const float* x      = (const float*)d_in[0];
    const float* maa_x  = (const float*)d_in[1];
    const float* maa_w  = (const float*)d_in[2];
    const float* maa_k  = (const float*)d_in[3];
    const float* maa_v  = (const float*)d_in[4];
    const float* maa_r  = (const float*)d_in[5];
    const float* maa_g  = (const float*)d_in[6];
    const float* maa_w1 = (const float*)d_in[7];
    const float* maa_w2 = (const float*)d_in[8];
    const float* tdecay = (const float*)d_in[9];
    const float* dw1    = (const float*)d_in[10];
    const float* dw2    = (const float*)d_in[11];
    const float* u      = (const float*)d_in[12];
    const float* W_r    = (const float*)d_in[13];
    const float* W_k    = (const float*)d_in[14];
    const float* W_v    = (const float*)d_in[15];
    const float* W_g    = (const float*)d_in[16];
    const float* W_o    = (const float*)d_in[17];
    const float* gamma  = (const float*)d_in[18];
    const float* beta   = (const float*)d_in[19];
    float* out = (float*)d_out;

    float *xx, *xxx, *m, *xw, *xk, *xv, *xr, *xg;
    float *rr, *kk, *vv, *gg, *ww, *t64, *y, *z;
    float *wt5, *w1t, *w2t, *dw1t, *dw2t;
    cudaGetSymbolAddress((void**)&xx,   g_xx);
    cudaGetSymbolAddress((void**)&xxx,  g_xxx);
    cudaGetSymbolAddress((void**)&m,    g_m);
    cudaGetSymbolAddress((void**)&xw,   g_xw);
    cudaGetSymbolAddress((void**)&xk,   g_xk);
    cudaGetSymbolAddress((void**)&xv,   g_xv);
    cudaGetSymbolAddress((void**)&xr,   g_xr);
    cudaGetSymbolAddress((void**)&xg,   g_xg);
    cudaGetSymbolAddress((void**)&rr,   g_r);
    cudaGetSymbolAddress((void**)&kk,   g_k);
    cudaGetSymbolAddress((void**)&vv,   g_v);
    cudaGetSymbolAddress((void**)&gg,   g_g);
    cudaGetSymbolAddress((void**)&ww,   g_w);
    cudaGetSymbolAddress((void**)&t64,  g_t64);
    cudaGetSymbolAddress((void**)&y,    g_y);
    cudaGetSymbolAddress((void**)&z,    g_z);
    cudaGetSymbolAddress((void**)&wt5,  g_wt5);
    cudaGetSymbolAddress((void**)&w1t,  g_w1t);
    cudaGetSymbolAddress((void**)&w2t,  g_w2t);
    cudaGetSymbolAddress((void**)&dw1t, g_dw1t);
    cudaGetSymbolAddress((void**)&dw2t, g_dw2t);

    cudaFuncSetAttribute(gemm_mma_kernel,
                         cudaFuncAttributeMaxDynamicSharedMemorySize, GSMEM_BYTES);

    const size_t WSZ = (size_t)Cc * Cc;
    dim3 tb(32, 8);

    // 0) weight transposes (full fp32)
    transpose_kernel<<<dim3(32, 32), tb>>>(W_r, wt5 + 0 * WSZ, 1024, 1024);
    transpose_kernel<<<dim3(32, 32), tb>>>(W_k, wt5 + 1 * WSZ, 1024, 1024);
    transpose_kernel<<<dim3(32, 32), tb>>>(W_v, wt5 + 2 * WSZ, 1024, 1024);
    transpose_kernel<<<dim3(32, 32), tb>>>(W_g, wt5 + 3 * WSZ, 1024, 1024);
    transpose_kernel<<<dim3(32, 32), tb>>>(W_o, wt5 + 4 * WSZ, 1024, 1024);
    transpose_kernel<<<dim3(5, 32),  tb>>>(maa_w1, w1t, 1024, 160);
    for (int f = 0; f < 5; f++)
        transpose_kernel<<<dim3(32, 1), tb>>>(
            maa_w2 + (size_t)f * 32 * 1024, w2t + (size_t)f * 1024 * 32, 32, 1024);
    transpose_kernel<<<dim3(2, 32), tb>>>(dw1, dw1t, 1024, 64);
    transpose_kernel<<<dim3(32, 2), tb>>>(dw2, dw2t, 64, 1024);

    // 1) token shift
    shift_kernel<<<(MT * Cc + 255) / 256, 256>>>(x, maa_x, xx, xxx);

    // 2) m = tanh(xxx @ W1)   [4096 x 160 x 1024]
    {
        GemmBatch a = {};
        a.A[0] = xxx; a.B[0] = w1t; a.C[0] = m;
        a.N[0] = 160; a.ldc[0] = 160; a.epi[0] = EPI_TANH;
        a.K = 1024; a.lda = 1024; a.ldb = 1024;
        gemm_mma_kernel<<<dim3(2, 32, 1), 256, GSMEM_BYTES>>>(a);
    }

    // 3) five mixing GEMMs, batched  [4096 x 1024 x 32] x5
    {
        GemmBatch a = {};
        const float* bias5[5] = {maa_w, maa_k, maa_v, maa_r, maa_g};
        float*       out5[5]  = {xw, xk, xv, xr, xg};
        for (int f = 0; f < 5; f++) {
            a.A[f] = m + f * 32;
            a.B[f] = w2t + (size_t)f * 1024 * 32;
            a.C[f] = out5[f];
            a.bias[f] = bias5[f];
            a.N[f] = 1024; a.ldc[f] = 1024; a.epi[f] = EPI_MIX;
        }
        a.ex = x; a.exx = xx;
        a.K = 32; a.lda = 160; a.ldb = 32;
        gemm_mma_kernel<<<dim3(8, 32, 5), 256, GSMEM_BYTES>>>(a);
    }

    // 4) projections r/k/v/g + decay LoRA-1, batched  (K=1024)
    {
        GemmBatch a = {};
        const float* As[5] = {xr, xk, xv, xg, xw};
        const float* Bs[5] = {wt5 + 0 * WSZ, wt5 + 1 * WSZ, wt5 + 2 * WSZ,
                              wt5 + 3 * WSZ, dw1t};
        float* Cs[5] = {rr, kk, vv, gg, t64};
        int Ns[5]   = {1024, 1024, 1024, 1024, 64};
        int ldcs[5] = {1024, 1024, 1024, 1024, 64};
        int epis[5] = {EPI_NONE, EPI_NONE, EPI_NONE, EPI_SILU, EPI_TANH};
        for (int f = 0; f < 5; f++) {
            a.A[f] = As[f]; a.B[f] = Bs[f]; a.C[f] = Cs[f];
            a.N[f] = Ns[f]; a.ldc[f] = ldcs[f]; a.epi[f] = epis[f];
        }
        a.K = 1024; a.lda = 1024; a.ldb = 1024;
        gemm_mma_kernel<<<dim3(8, 32, 5), 256, GSMEM_BYTES>>>(a);
    }

    // 5) decay LoRA-2: w = time_decay + t64 @ dw2   [4096 x 1024 x 64]
    {
        GemmBatch a = {};
        a.A[0] = t64; a.B[0] = dw2t; a.C[0] = ww; a.bias[0] = tdecay;
        a.N[0] = 1024; a.ldc[0] = 1024; a.epi[0] = EPI_BIAS;
        a.K = 64; a.lda = 64; a.ldb = 64;
        gemm_mma_kernel<<<dim3(8, 32, 1), 256, GSMEM_BYTES>>>(a);
    }

    // 6) WKV6 scan
    wkv6_kernel<<<Bc * Hh, 64>>>(rr, kk, vv, ww, u, y);

    // 7) groupnorm + gate
    gnorm_kernel<<<MT, 256>>>(y, gg, gamma, beta, z);

    // 8) output projection  [4096 x 1024 x 1024]
    {
        GemmBatch a = {};
        a.A[0] = z; a.B[0] = wt5 + 4 * WSZ; a.C[0] = out;
        a.N[0] = 1024; a.ldc[0] = 1024; a.epi[0] = EPI_NONE;
        a.K = 1024; a.lda = 1024; a.ldb = 1024;
        gemm_mma_kernel<<<dim3(8, 32, 1), 256, GSMEM_BYTES>>>(a);
    }
}

// round 9
// speedup vs baseline: 1.8589x; 1.4810x over previous
#include <cuda_runtime.h>
#include <math.h>
#include <stdint.h>

// ---------------------------------------------------------------------------
// RWKV v6 TimeMix  (B=4, T=1024, C=1024, H=16, K=64)
// Round 9: chunked WKV6 scan (16 chunks x 64 steps, 3-pass state handoff).
// GEMMs unchanged from R8 (3xTF32 mma.sync + cp.async pipeline).
// ---------------------------------------------------------------------------

#define Bc 4
#define Tc 1024
#define Cc 1024
#define Hh 16
#define Kk 64
#define MT (Bc * Tc)          // 4096 rows
#define EPSC (1e-5f * 64.0f)
#define NCHUNK 16
#define CLEN   64             // Tc / NCHUNK

// ------------------------- scratch (static device mem) ---------------------
__device__ float g_xx  [MT * Cc];
__device__ float g_xxx [MT * Cc];
__device__ float g_m   [MT * 160];
__device__ float g_xw  [MT * Cc];
__device__ float g_xk  [MT * Cc];
__device__ float g_xv  [MT * Cc];
__device__ float g_xr  [MT * Cc];
__device__ float g_xg  [MT * Cc];
__device__ float g_r   [MT * Cc];
__device__ float g_k   [MT * Cc];
__device__ float g_v   [MT * Cc];
__device__ float g_g   [MT * Cc];
__device__ float g_w   [MT * Cc];      // w in, overwritten with wd=exp(-exp(w))
__device__ float g_t64 [MT * 64];
__device__ float g_y   [MT * Cc];
__device__ float g_z   [MT * Cc];
__device__ float g_wt5 [5 * Cc * Cc];
__device__ float g_w1t [160 * Cc];
__device__ float g_w2t [5 * Cc * 32];
__device__ float g_dw1t[64 * Cc];
__device__ float g_dw2t[Cc * 64];
__device__ float g_sc  [64 * NCHUNK * Kk * Kk];  // chunk states, 16.7MB
__device__ float g_dp  [64 * NCHUNK * Kk];       // chunk decay products

// ======================= 3xTF32 mma.sync GEMM ==============================
enum { EPI_NONE = 0, EPI_TANH = 1, EPI_SILU = 2, EPI_BIAS = 3, EPI_MIX = 4 };

struct GemmBatch {
    const float* A[5];
    const float* B[5];
    float*       C[5];
    const float* bias[5];
    int          N[5];
    int          ldc[5];
    int          epi[5];
    const float* ex;
    const float* exx;
    int K, lda, ldb;
};

#define GSTAGE_FLOATS 9216
#define GSTAGE_BYTES  36864u
#define GSMEM_BYTES   (4u * GSTAGE_BYTES)

__device__ __forceinline__ void cp16(uint32_t saddr, const void* gptr, int sz) {
    asm volatile("cp.async.cg.shared.global [%0], [%1], 16, %2;"
                 :: "r"(saddr), "l"(gptr), "r"(sz));
}
__device__ __forceinline__ void cp_commit() {
    asm volatile("cp.async.commit_group;" ::: "memory");
}
__device__ __forceinline__ void cp_wait2() {
    asm volatile("cp.async.wait_group 2;" ::: "memory");
}
__device__ __forceinline__ uint32_t smem_u32(const void* p) {
    uint32_t a;
    asm("{ .reg .u64 t; cvta.to.shared.u64 t, %1; cvt.u32.u64 %0, t; }"
        : "=r"(a) : "l"(p));
    return a;
}
__device__ __forceinline__ void split_tf32(float v, uint32_t& hi, uint32_t& lo) {
    asm("cvt.rna.tf32.f32 %0, %1;" : "=r"(hi) : "f"(v));
    float d = v - __uint_as_float(hi);
    asm("cvt.rna.tf32.f32 %0, %1;" : "=r"(lo) : "f"(d));
}
__device__ __forceinline__ void mma_tf32_16n8k8(float c[4],
    uint32_t a0, uint32_t a1, uint32_t a2, uint32_t a3, uint32_t b0, uint32_t b1)
{
    asm volatile(
        "mma.sync.aligned.m16n8k8.row.col.f32.tf32.tf32.f32 "
        "{%0,%1,%2,%3}, {%4,%5,%6,%7}, {%8,%9}, {%0,%1,%2,%3};"
        : "+f"(c[0]), "+f"(c[1]), "+f"(c[2]), "+f"(c[3])
        : "r"(a0), "r"(a1), "r"(a2), "r"(a3), "r"(b0), "r"(b1));
}

__global__ void __launch_bounds__(256, 1)
gemm_mma_kernel(const GemmBatch args)
{
    extern __shared__ float smem[];
    const int z  = blockIdx.z;
    const int Nz = args.N[z];
    const int n0 = blockIdx.x * 128;
    if (n0 >= Nz) return;
    const int m0 = blockIdx.y * 128;

    const int tid = threadIdx.x;
    const int wid = tid >> 5;
    const int lid = tid & 31;
    const int wm  = wid >> 2;
    const int wn  = wid & 3;
    const int gid = lid >> 2;
    const int tig = lid & 3;

    const float* Ag = args.A[z];
    const float* Bg = args.B[z];
    const int lda = args.lda, ldb = args.ldb, K = args.K;
    const int NIT = K >> 5;

    const int arow = tid >> 1;
    const int acol = (tid & 1) * 16;
    const uint32_t sbase = smem_u32(smem);
    const int brow_ok = (n0 + arow) < Nz;
    const int bsz = brow_ok ? 16 : 0;
    const float* gArow = Ag + (size_t)(m0 + arow) * lda + acol;
    const float* gBrow = Bg + (size_t)(brow_ok ? (n0 + arow) : 0) * ldb + acol;

    auto load_stage = [&](int stage, int kt) {
        const uint32_t sA = sbase + (uint32_t)stage * GSTAGE_BYTES
                          + (uint32_t)(arow * 36 + acol) * 4u;
        const uint32_t sB = sA + 18432u;
        const float* ga = gArow + kt * 32;
        const float* gb = gBrow + kt * 32;
#pragma unroll
        for (int i = 0; i < 4; i++) cp16(sA + i * 16u, ga + i * 4, 16);
#pragma unroll
        for (int i = 0; i < 4; i++) cp16(sB + i * 16u, gb + i * 4, bsz);
    };

    float c[4][4][4];
#pragma unroll
    for (int mt = 0; mt < 4; mt++)
#pragma unroll
        for (int nt = 0; nt < 4; nt++)
#pragma unroll
            for (int i = 0; i < 4; i++) c[mt][nt][i] = 0.0f;

#pragma unroll
    for (int p = 0; p < 3; p++) {
        if (p < NIT) load_stage(p, p);
        cp_commit();
    }

    for (int kt = 0; kt < NIT; kt++) {
        cp_wait2();
        __syncthreads();

        const float* As  = smem + (kt & 3) * GSTAGE_FLOATS;
        const float* Bs  = As + 4608;
        const int    am  = wm * 64 + gid;
        const int    bn  = wn * 32 + gid;

#pragma unroll
        for (int ks = 0; ks < 4; ks++) {
            const int k0 = ks * 8 + tig;
            uint32_t bh[4][2], bl[4][2];
#pragma unroll
            for (int nt = 0; nt < 4; nt++) {
                const float* bp = Bs + (bn + nt * 8) * 36 + k0;
                split_tf32(bp[0], bh[nt][0], bl[nt][0]);
                split_tf32(bp[4], bh[nt][1], bl[nt][1]);
            }
#pragma unroll
            for (int mt = 0; mt < 4; mt++) {
                const float* ap = As + (am + mt * 16) * 36 + k0;
                uint32_t ah[4], al[4];
                split_tf32(ap[0],          ah[0], al[0]);
                split_tf32(ap[8 * 36],     ah[1], al[1]);
                split_tf32(ap[4],          ah[2], al[2]);
                split_tf32(ap[8 * 36 + 4], ah[3], al[3]);
#pragma unroll
                for (int nt = 0; nt < 4; nt++) {
                    mma_tf32_16n8k8(c[mt][nt], ah[0], ah[1], ah[2], ah[3],
                                    bh[nt][0], bh[nt][1]);
                    mma_tf32_16n8k8(c[mt][nt], ah[0], ah[1], ah[2], ah[3],
                                    bl[nt][0], bl[nt][1]);
                    mma_tf32_16n8k8(c[mt][nt], al[0], al[1], al[2], al[3],
                                    bh[nt][0], bh[nt][1]);
                }
            }
        }
        __syncthreads();
        const int j = kt + 3;
        if (j < NIT) load_stage(j & 3, j);
        cp_commit();
    }

    const int ep = args.epi[z];
    const float* bias = args.bias[z];
    float* Cg = args.C[z];
    const int ldc = args.ldc[z];
    const float* ex  = args.ex;
    const float* exx = args.exx;

    auto apply2 = [&](float& v0, float& v1, int row, int col) {
        if (ep == EPI_TANH) { v0 = tanhf(v0); v1 = tanhf(v1); }
        else if (ep == EPI_SILU) {
            v0 = v0 / (1.0f + expf(-v0));
            v1 = v1 / (1.0f + expf(-v1));
        } else if (ep == EPI_BIAS) { v0 += bias[col]; v1 += bias[col + 1]; }
        else if (ep == EPI_MIX) {
            size_t idx = (size_t)row * 1024 + col;
            float2 e  = *reinterpret_cast<const float2*>(ex  + idx);
            float2 dx = *reinterpret_cast<const float2*>(exx + idx);
            v0 = e.x + dx.x * (bias[col]     + v0);
            v1 = e.y + dx.y * (bias[col + 1] + v1);
        }
    };

#pragma unroll
    for (int mt = 0; mt < 4; mt++) {
        const int r0 = m0 + wm * 64 + mt * 16 + gid;
#pragma unroll
        for (int nt = 0; nt < 4; nt++) {
            const int col = n0 + wn * 32 + nt * 8 + tig * 2;
            if (col < Nz) {
                float v0 = c[mt][nt][0], v1 = c[mt][nt][1];
                apply2(v0, v1, r0, col);
                *reinterpret_cast<float2*>(Cg + (size_t)r0 * ldc + col)
                    = make_float2(v0, v1);
                float v2 = c[mt][nt][2], v3 = c[mt][nt][3];
                apply2(v2, v3, r0 + 8, col);
                *reinterpret_cast<float2*>(Cg + (size_t)(r0 + 8) * ldc + col)
                    = make_float2(v2, v3);
            }
        }
    }
}

// ------------------------- generic fp32 transpose --------------------------
__global__ void transpose_kernel(const float* __restrict__ src,
                                 float* __restrict__ dst, int R, int C)
{
    __shared__ float tile[32][33];
    const int bx = blockIdx.x * 32, by = blockIdx.y * 32;
    const int tx = threadIdx.x, ty = threadIdx.y;
#pragma unroll
    for (int r = 0; r < 32; r += 8)
        tile[ty + r][tx] = src[(size_t)(by + ty + r) * C + bx + tx];
    __syncthreads();
#pragma unroll
    for (int r = 0; r < 32; r += 8)
        dst[(size_t)(bx + ty + r) * R + by + tx] = tile[tx][ty + r];
}

// ------------------------- elementwise: token shift ------------------------
__global__ void shift_kernel(const float* __restrict__ x,
                             const float* __restrict__ maa_x,
                             float* __restrict__ xx,
                             float* __restrict__ xxx)
{
    int i = blockIdx.x * blockDim.x + threadIdx.x;
    if (i >= MT * Cc) return;
    int c = i & (Cc - 1);
    int t = (i >> 10) & (Tc - 1);
    float xv = x[i];
    float xp = (t != 0) ? x[i - Cc] : 0.0f;
    float d  = xp - xv;
    xx[i]  = d;
    xxx[i] = xv + d * maa_x[c];
}

// ==================== chunked WKV6 (3 passes) ==============================
// Pass 1: per (bh, chunk): local state from zero + per-channel decay product.
// Also converts w -> wd = exp(-exp(w)) IN PLACE (each elem read then written
// by the same thread).
__global__ __launch_bounds__(64)
void wkv6_pass1_kernel(const float* __restrict__ k, const float* __restrict__ v,
                       float* __restrict__ w, float* __restrict__ sc,
                       float* __restrict__ dp)
{
    const int bh = blockIdx.x >> 4;     // 0..63
    const int c  = blockIdx.x & 15;     // chunk
    const int b  = bh >> 4;
    const int h  = bh & 15;
    const int j  = threadIdx.x;
    const size_t base = (size_t)b * Tc * Cc + h * Kk + j;

    float S[64];
#pragma unroll
    for (int i = 0; i < 64; i++) S[i] = 0.0f;
    float Dj = 1.0f;

    __shared__ float2 q[64];   // {k_i, wd_i}

    const int t0 = c * CLEN;
    for (int t = t0; t < t0 + CLEN; t++) {
        const size_t off = base + (size_t)t * Cc;
        float kj = k[off];
        float vj = v[off];
        float wj = w[off];
        float wd = expf(-expf(wj));
        w[off] = wd;
        Dj *= wd;
        q[j] = make_float2(kj, wd);
        __syncthreads();
#pragma unroll
        for (int i = 0; i < 64; i += 4) {
            float2 q0 = q[i + 0], q1 = q[i + 1], q2 = q[i + 2], q3 = q[i + 3];
            S[i + 0] = fmaf(S[i + 0], q0.y, q0.x * vj);
            S[i + 1] = fmaf(S[i + 1], q1.y, q1.x * vj);
            S[i + 2] = fmaf(S[i + 2], q2.y, q2.x * vj);
            S[i + 3] = fmaf(S[i + 3], q3.y, q3.x * vj);
        }
        __syncthreads();
    }

    float* scp = sc + ((size_t)bh * NCHUNK + c) * (Kk * Kk);
#pragma unroll 8
    for (int i = 0; i < 64; i++) scp[i * 64 + j] = S[i];
    dp[((size_t)bh * NCHUNK + c) * Kk + j] = Dj;
}

// Pass 2: sequential chunk recombination. Replaces sc[c] (local state) with
// the chunk-START state: R(0)=0; sc[c] <- R(c); R(c+1) = R(c) (.) D(c) + local(c).
__global__ __launch_bounds__(64)
void wkv6_pass2_kernel(float* __restrict__ sc, const float* __restrict__ dp)
{
    const int bh = blockIdx.x;
    const int j  = threadIdx.x;

    float R[64];
#pragma unroll
    for (int i = 0; i < 64; i++) R[i] = 0.0f;

    __shared__ float Ds[64];

    for (int c = 0; c < NCHUNK; c++) {
        Ds[j] = dp[((size_t)bh * NCHUNK + c) * Kk + j];
        __syncthreads();
        float* scp = sc + ((size_t)bh * NCHUNK + c) * (Kk * Kk);
#pragma unroll 4
        for (int i = 0; i < 64; i++) {
            float sl = scp[i * 64 + j];
            scp[i * 64 + j] = R[i];
            R[i] = fmaf(R[i], Ds[i], sl);
        }
        __syncthreads();
    }
}

// Pass 3: per (bh, chunk): y-producing scan starting from the chunk-start
// state. wd is read pre-computed (pass 1 stored it in place of w).
__global__ __launch_bounds__(64)
void wkv6_pass3_kernel(const float* __restrict__ r, const float* __restrict__ k,
                       const float* __restrict__ v, const float* __restrict__ wd,
                       const float* __restrict__ u, const float* __restrict__ sc,
                       float* __restrict__ y)
{
    const int bh = blockIdx.x >> 4;
    const int c  = blockIdx.x & 15;
    const int b  = bh >> 4;
    const int h  = bh & 15;
    const int j  = threadIdx.x;
    const size_t base = (size_t)b * Tc * Cc + h * Kk + j;
    const float  uj   = u[h * Kk + j];

    float S[64];
    const float* scp = sc + ((size_t)bh * NCHUNK + c) * (Kk * Kk);
#pragma unroll 8
    for (int i = 0; i < 64; i++) S[i] = scp[i * 64 + j];

    __shared__ float4 q[64];   // {r, k, wd, u}

    const int t0 = c * CLEN;
    for (int t = t0; t < t0 + CLEN; t++) {
        const size_t off = base + (size_t)t * Cc;
        float rj = r[off];
        float kj = k[off];
        float dj = wd[off];
        float vj = v[off];
        q[j] = make_float4(rj, kj, dj, uj);
        __syncthreads();

        float y0 = 0.f, y1 = 0.f, y2 = 0.f, y3 = 0.f;
#pragma unroll
        for (int kk = 0; kk < 64; kk += 4) {
            float4 q0 = q[kk + 0];
            float4 q1 = q[kk + 1];
            float4 q2 = q[kk + 2];
            float4 q3 = q[kk + 3];
            float kv0 = q0.y * vj;
            float kv1 = q1.y * vj;
            float kv2 = q2.y * vj;
            float kv3 = q3.y * vj;
            y0 = fmaf(q0.x, fmaf(q0.w, kv0, S[kk + 0]), y0);
            y1 = fmaf(q1.x, fmaf(q1.w, kv1, S[kk + 1]), y1);
            y2 = fmaf(q2.x, fmaf(q2.w, kv2, S[kk + 2]), y2);
            y3 = fmaf(q3.x, fmaf(q3.w, kv3, S[kk + 3]), y3);
            S[kk + 0] = fmaf(S[kk + 0], q0.z, kv0);
            S[kk + 1] = fmaf(S[kk + 1], q1.z, kv1);
            S[kk + 2] = fmaf(S[kk + 2], q2.z, kv2);
            S[kk + 3] = fmaf(S[kk + 3], q3.z, kv3);
        }
        y[off] = (y0 + y1) + (y2 + y3);
        __syncthreads();
    }
}

// ------------------------- groupnorm + gate --------------------------------
__global__ __launch_bounds__(256)
void gnorm_kernel(const float* __restrict__ y, const float* __restrict__ gate,
                  const float* __restrict__ gamma, const float* __restrict__ beta,
                  float* __restrict__ z)
{
    const int row = blockIdx.x;
    const int tid = threadIdx.x;
    const int c0  = tid * 4;
    const size_t idx = (size_t)row * Cc + c0;

    float4 yv = *reinterpret_cast<const float4*>(y + idx);
    float s  = yv.x + yv.y + yv.z + yv.w;
    float ss = yv.x * yv.x + yv.y * yv.y + yv.z * yv.z + yv.w * yv.w;
#pragma unroll
    for (int o = 8; o > 0; o >>= 1) {
        s  += __shfl_xor_sync(0xffffffffu, s,  o);
        ss += __shfl_xor_sync(0xffffffffu, ss, o);
    }
    const float mean = s * (1.0f / 64.0f);
    const float var  = ss * (1.0f / 64.0f) - mean * mean;
    const float rstd = rsqrtf(var + EPSC);

    float4 gm = *reinterpret_cast<const float4*>(gamma + c0);
    float4 bt = *reinterpret_cast<const float4*>(beta + c0);
    float4 gt = *reinterpret_cast<const float4*>(gate + idx);
    float4 o;
    o.x = ((yv.x - mean) * rstd * gm.x + bt.x) * gt.x;
    o.y = ((yv.y - mean) * rstd * gm.y + bt.y) * gt.y;
    o.z = ((yv.z - mean) * rstd * gm.z + bt.z) * gt.z;
    o.w = ((yv.w - mean) * rstd * gm.w + bt.w) * gt.w;
    *reinterpret_cast<float4*>(z + idx) = o;
}

// ---------------------------------------------------------------------------
extern "C" void kernel_launch(void* const* d_in, const int* in_sizes, int n_in,
                              void* d_out, int out_size)
{
    const float* x      = (const float*)d_in[0];
    const float* maa_x  = (const float*)d_in[1];
    const float* maa_w  = (const float*)d_in[2];
    const float* maa_k  = (const float*)d_in[3];
    const float* maa_v  = (const float*)d_in[4];
    const float* maa_r  = (const float*)d_in[5];
    const float* maa_g  = (const float*)d_in[6];
    const float* maa_w1 = (const float*)d_in[7];
    const float* maa_w2 = (const float*)d_in[8];
    const float* tdecay = (const float*)d_in[9];
    const float* dw1    = (const float*)d_in[10];
    const float* dw2    = (const float*)d_in[11];
    const float* u      = (const float*)d_in[12];
    const float* W_r    = (const float*)d_in[13];
    const float* W_k    = (const float*)d_in[14];
    const float* W_v    = (const float*)d_in[15];
    const float* W_g    = (const float*)d_in[16];
    const float* W_o    = (const float*)d_in[17];
    const float* gamma  = (const float*)d_in[18];
    const float* beta   = (const float*)d_in[19];
    float* out = (float*)d_out;

    float *xx, *xxx, *m, *xw, *xk, *xv, *xr, *xg;
    float *rr, *kk, *vv, *gg, *ww, *t64, *y, *z;
    float *wt5, *w1t, *w2t, *dw1t, *dw2t, *sc, *dpp;
    cudaGetSymbolAddress((void**)&xx,   g_xx);
    cudaGetSymbolAddress((void**)&xxx,  g_xxx);
    cudaGetSymbolAddress((void**)&m,    g_m);
    cudaGetSymbolAddress((void**)&xw,   g_xw);
    cudaGetSymbolAddress((void**)&xk,   g_xk);
    cudaGetSymbolAddress((void**)&xv,   g_xv);
    cudaGetSymbolAddress((void**)&xr,   g_xr);
    cudaGetSymbolAddress((void**)&xg,   g_xg);
    cudaGetSymbolAddress((void**)&rr,   g_r);
    cudaGetSymbolAddress((void**)&kk,   g_k);
    cudaGetSymbolAddress((void**)&vv,   g_v);
    cudaGetSymbolAddress((void**)&gg,   g_g);
    cudaGetSymbolAddress((void**)&ww,   g_w);
    cudaGetSymbolAddress((void**)&t64,  g_t64);
    cudaGetSymbolAddress((void**)&y,    g_y);
    cudaGetSymbolAddress((void**)&z,    g_z);
    cudaGetSymbolAddress((void**)&wt5,  g_wt5);
    cudaGetSymbolAddress((void**)&w1t,  g_w1t);
    cudaGetSymbolAddress((void**)&w2t,  g_w2t);
    cudaGetSymbolAddress((void**)&dw1t, g_dw1t);
    cudaGetSymbolAddress((void**)&dw2t, g_dw2t);
    cudaGetSymbolAddress((void**)&sc,   g_sc);
    cudaGetSymbolAddress((void**)&dpp,  g_dp);

    cudaFuncSetAttribute(gemm_mma_kernel,
                         cudaFuncAttributeMaxDynamicSharedMemorySize, GSMEM_BYTES);

    const size_t WSZ = (size_t)Cc * Cc;
    dim3 tb(32, 8);

    // 0) weight transposes (full fp32)
    transpose_kernel<<<dim3(32, 32), tb>>>(W_r, wt5 + 0 * WSZ, 1024, 1024);
    transpose_kernel<<<dim3(32, 32), tb>>>(W_k, wt5 + 1 * WSZ, 1024, 1024);
    transpose_kernel<<<dim3(32, 32), tb>>>(W_v, wt5 + 2 * WSZ, 1024, 1024);
    transpose_kernel<<<dim3(32, 32), tb>>>(W_g, wt5 + 3 * WSZ, 1024, 1024);
    transpose_kernel<<<dim3(32, 32), tb>>>(W_o, wt5 + 4 * WSZ, 1024, 1024);
    transpose_kernel<<<dim3(5, 32),  tb>>>(maa_w1, w1t, 1024, 160);
    for (int f = 0; f < 5; f++)
        transpose_kernel<<<dim3(32, 1), tb>>>(
            maa_w2 + (size_t)f * 32 * 1024, w2t + (size_t)f * 1024 * 32, 32, 1024);
    transpose_kernel<<<dim3(2, 32), tb>>>(dw1, dw1t, 1024, 64);
    transpose_kernel<<<dim3(32, 2), tb>>>(dw2, dw2t, 64, 1024);

    // 1) token shift
    shift_kernel<<<(MT * Cc + 255) / 256, 256>>>(x, maa_x, xx, xxx);

    // 2) m = tanh(xxx @ W1)   [4096 x 160 x 1024]
    {
        GemmBatch a = {};
        a.A[0] = xxx; a.B[0] = w1t; a.C[0] = m;
        a.N[0] = 160; a.ldc[0] = 160; a.epi[0] = EPI_TANH;
        a.K = 1024; a.lda = 1024; a.ldb = 1024;
        gemm_mma_kernel<<<dim3(2, 32, 1), 256, GSMEM_BYTES>>>(a);
    }

    // 3) five mixing GEMMs, batched  [4096 x 1024 x 32] x5
    {
        GemmBatch a = {};
        const float* bias5[5] = {maa_w, maa_k, maa_v, maa_r, maa_g};
        float*       out5[5]  = {xw, xk, xv, xr, xg};
        for (int f = 0; f < 5; f++) {
            a.A[f] = m + f * 32;
            a.B[f] = w2t + (size_t)f * 1024 * 32;
            a.C[f] = out5[f];
            a.bias[f] = bias5[f];
            a.N[f] = 1024; a.ldc[f] = 1024; a.epi[f] = EPI_MIX;
        }
        a.ex = x; a.exx = xx;
        a.K = 32; a.lda = 160; a.ldb = 32;
        gemm_mma_kernel<<<dim3(8, 32, 5), 256, GSMEM_BYTES>>>(a);
    }

    // 4) projections r/k/v/g + decay LoRA-1, batched  (K=1024)
    {
        GemmBatch a = {};
        const float* As[5] = {xr, xk, xv, xg, xw};
        const float* Bs[5] = {wt5 + 0 * WSZ, wt5 + 1 * WSZ, wt5 + 2 * WSZ,
                              wt5 + 3 * WSZ, dw1t};
        float* Cs[5] = {rr, kk, vv, gg, t64};
        int Ns[5]   = {1024, 1024, 1024, 1024, 64};
        int ldcs[5] = {1024, 1024, 1024, 1024, 64};
        int epis[5] = {EPI_NONE, EPI_NONE, EPI_NONE, EPI_SILU, EPI_TANH};
        for (int f = 0; f < 5; f++) {
            a.A[f] = As[f]; a.B[f] = Bs[f]; a.C[f] = Cs[f];
            a.N[f] = Ns[f]; a.ldc[f] = ldcs[f]; a.epi[f] = epis[f];
        }
        a.K = 1024; a.lda = 1024; a.ldb = 1024;
        gemm_mma_kernel<<<dim3(8, 32, 5), 256, GSMEM_BYTES>>>(a);
    }

    // 5) decay LoRA-2: w = time_decay + t64 @ dw2   [4096 x 1024 x 64]
    {
        GemmBatch a = {};
        a.A[0] = t64; a.B[0] = dw2t; a.C[0] = ww; a.bias[0] = tdecay;
        a.N[0] = 1024; a.ldc[0] = 1024; a.epi[0] = EPI_BIAS;
        a.K = 64; a.lda = 64; a.ldb = 64;
        gemm_mma_kernel<<<dim3(8, 32, 1), 256, GSMEM_BYTES>>>(a);
    }

    // 6) chunked WKV6 scan (3 passes)
    wkv6_pass1_kernel<<<64 * NCHUNK, 64>>>(kk, vv, ww, sc, dpp);
    wkv6_pass2_kernel<<<64, 64>>>(sc, dpp);
    wkv6_pass3_kernel<<<64 * NCHUNK, 64>>>(rr, kk, vv, ww, u, sc, y);

    // 7) groupnorm + gate
    gnorm_kernel<<<MT, 256>>>(y, gg, gamma, beta, z);

    // 8) output projection  [4096 x 1024 x 1024]
    {
        GemmBatch a = {};
        a.A[0] = z; a.B[0] = wt5 + 4 * WSZ; a.C[0] = out;
        a.N[0] = 1024; a.ldc[0] = 1024; a.epi[0] = EPI_NONE;
        a.K = 1024; a.lda = 1024; a.ldb = 1024;
        gemm_mma_kernel<<<dim3(8, 32, 1), 256, GSMEM_BYTES>>>(a);
    }
}

// round 10
// speedup vs baseline: 2.0169x; 1.0850x over previous
#include <cuda_runtime.h>
#include <math.h>
#include <stdint.h>

// ---------------------------------------------------------------------------
// RWKV v6 TimeMix  (B=4, T=1024, C=1024, H=16, K=64)
// Round 10: 3-stage cp.async pipeline + 2 CTAs/SM on the 3xTF32 GEMM
// (latency-hiding theory); transposes batched into 2 launches so ncu's
// "-s 5 -c 1" captures the big projection GEMM. WKV chunked scan from R9.
// ---------------------------------------------------------------------------

#define Bc 4
#define Tc 1024
#define Cc 1024
#define Hh 16
#define Kk 64
#define MT (Bc * Tc)          // 4096 rows
#define EPSC (1e-5f * 64.0f)
#define NCHUNK 16
#define CLEN   64             // Tc / NCHUNK

// ------------------------- scratch (static device mem) ---------------------
__device__ float g_xx  [MT * Cc];
__device__ float g_xxx [MT * Cc];
__device__ float g_m   [MT * 160];
__device__ float g_xw  [MT * Cc];
__device__ float g_xk  [MT * Cc];
__device__ float g_xv  [MT * Cc];
__device__ float g_xr  [MT * Cc];
__device__ float g_xg  [MT * Cc];
__device__ float g_r   [MT * Cc];
__device__ float g_k   [MT * Cc];
__device__ float g_v   [MT * Cc];
__device__ float g_g   [MT * Cc];
__device__ float g_w   [MT * Cc];      // w in, overwritten with wd=exp(-exp(w))
__device__ float g_t64 [MT * 64];
__device__ float g_y   [MT * Cc];
__device__ float g_z   [MT * Cc];
__device__ float g_wt5 [5 * Cc * Cc];
__device__ float g_w1t [160 * Cc];
__device__ float g_w2t [5 * Cc * 32];
__device__ float g_dw1t[64 * Cc];
__device__ float g_dw2t[Cc * 64];
__device__ float g_sc  [64 * NCHUNK * Kk * Kk];
__device__ float g_dp  [64 * NCHUNK * Kk];

// ======================= 3xTF32 mma.sync GEMM ==============================
enum { EPI_NONE = 0, EPI_TANH = 1, EPI_SILU = 2, EPI_BIAS = 3, EPI_MIX = 4 };

struct GemmBatch {
    const float* A[5];
    const float* B[5];
    float*       C[5];
    const float* bias[5];
    int          N[5];
    int          ldc[5];
    int          epi[5];
    const float* ex;
    const float* exx;
    int K, lda, ldb;
};

#define GSTAGE_FLOATS 9216            // (128*36)*2 per stage
#define GSTAGE_BYTES  36864u
#define GNST          3
#define GSMEM_BYTES   (3u * GSTAGE_BYTES)   // 110592

__device__ __forceinline__ void cp16(uint32_t saddr, const void* gptr, int sz) {
    asm volatile("cp.async.cg.shared.global [%0], [%1], 16, %2;"
                 :: "r"(saddr), "l"(gptr), "r"(sz));
}
__device__ __forceinline__ void cp_commit() {
    asm volatile("cp.async.commit_group;" ::: "memory");
}
__device__ __forceinline__ void cp_wait1() {
    asm volatile("cp.async.wait_group 1;" ::: "memory");
}
__device__ __forceinline__ uint32_t smem_u32(const void* p) {
    uint32_t a;
    asm("{ .reg .u64 t; cvta.to.shared.u64 t, %1; cvt.u32.u64 %0, t; }"
        : "=r"(a) : "l"(p));
    return a;
}
__device__ __forceinline__ void split_tf32(float v, uint32_t& hi, uint32_t& lo) {
    asm("cvt.rna.tf32.f32 %0, %1;" : "=r"(hi) : "f"(v));
    float d = v - __uint_as_float(hi);
    asm("cvt.rna.tf32.f32 %0, %1;" : "=r"(lo) : "f"(d));
}
__device__ __forceinline__ void mma_tf32_16n8k8(float c[4],
    uint32_t a0, uint32_t a1, uint32_t a2, uint32_t a3, uint32_t b0, uint32_t b1)
{
    asm volatile(
        "mma.sync.aligned.m16n8k8.row.col.f32.tf32.tf32.f32 "
        "{%0,%1,%2,%3}, {%4,%5,%6,%7}, {%8,%9}, {%0,%1,%2,%3};"
        : "+f"(c[0]), "+f"(c[1]), "+f"(c[2]), "+f"(c[3])
        : "r"(a0), "r"(a1), "r"(a2), "r"(a3), "r"(b0), "r"(b1));
}

__global__ void __launch_bounds__(256, 2)
gemm_mma_kernel(const GemmBatch args)
{
    extern __shared__ float smem[];
    const int z  = blockIdx.z;
    const int Nz = args.N[z];
    const int n0 = blockIdx.x * 128;
    if (n0 >= Nz) return;
    const int m0 = blockIdx.y * 128;

    const int tid = threadIdx.x;
    const int wid = tid >> 5;
    const int lid = tid & 31;
    const int wm  = wid >> 2;
    const int wn  = wid & 3;
    const int gid = lid >> 2;
    const int tig = lid & 3;

    const float* Ag = args.A[z];
    const float* Bg = args.B[z];
    const int lda = args.lda, ldb = args.ldb, K = args.K;
    const int NIT = K >> 5;

    const int arow = tid >> 1;
    const int acol = (tid & 1) * 16;
    const uint32_t sbase = smem_u32(smem);
    const int brow_ok = (n0 + arow) < Nz;
    const int bsz = brow_ok ? 16 : 0;
    const float* gArow = Ag + (size_t)(m0 + arow) * lda + acol;
    const float* gBrow = Bg + (size_t)(brow_ok ? (n0 + arow) : 0) * ldb + acol;

    auto load_stage = [&](int stage, int kt) {
        const uint32_t sA = sbase + (uint32_t)stage * GSTAGE_BYTES
                          + (uint32_t)(arow * 36 + acol) * 4u;
        const uint32_t sB = sA + 18432u;
        const float* ga = gArow + kt * 32;
        const float* gb = gBrow + kt * 32;
#pragma unroll
        for (int i = 0; i < 4; i++) cp16(sA + i * 16u, ga + i * 4, 16);
#pragma unroll
        for (int i = 0; i < 4; i++) cp16(sB + i * 16u, gb + i * 4, bsz);
    };

    float c[4][4][4];
#pragma unroll
    for (int mt = 0; mt < 4; mt++)
#pragma unroll
        for (int nt = 0; nt < 4; nt++)
#pragma unroll
            for (int i = 0; i < 4; i++) c[mt][nt][i] = 0.0f;

    // prologue: 2 stages ahead
#pragma unroll
    for (int p = 0; p < 2; p++) {
        if (p < NIT) load_stage(p, p);
        cp_commit();
    }

    for (int kt = 0; kt < NIT; kt++) {
        cp_wait1();              // all but newest group done -> stage kt ready
        __syncthreads();

        int st = kt % GNST;
        const float* As  = smem + st * GSTAGE_FLOATS;
        const float* Bs  = As + 4608;
        const int    am  = wm * 64 + gid;
        const int    bn  = wn * 32 + gid;

#pragma unroll
        for (int ks = 0; ks < 4; ks++) {
            const int k0 = ks * 8 + tig;
            uint32_t bh[4][2], bl[4][2];
#pragma unroll
            for (int nt = 0; nt < 4; nt++) {
                const float* bp = Bs + (bn + nt * 8) * 36 + k0;
                split_tf32(bp[0], bh[nt][0], bl[nt][0]);
                split_tf32(bp[4], bh[nt][1], bl[nt][1]);
            }
#pragma unroll
            for (int mt = 0; mt < 4; mt++) {
                const float* ap = As + (am + mt * 16) * 36 + k0;
                uint32_t ah[4], al[4];
                split_tf32(ap[0],          ah[0], al[0]);
                split_tf32(ap[8 * 36],     ah[1], al[1]);
                split_tf32(ap[4],          ah[2], al[2]);
                split_tf32(ap[8 * 36 + 4], ah[3], al[3]);
#pragma unroll
                for (int nt = 0; nt < 4; nt++) {
                    mma_tf32_16n8k8(c[mt][nt], ah[0], ah[1], ah[2], ah[3],
                                    bh[nt][0], bh[nt][1]);
                    mma_tf32_16n8k8(c[mt][nt], ah[0], ah[1], ah[2], ah[3],
                                    bl[nt][0], bl[nt][1]);
                    mma_tf32_16n8k8(c[mt][nt], al[0], al[1], al[2], al[3],
                                    bh[nt][0], bh[nt][1]);
                }
            }
        }
        __syncthreads();
        const int j = kt + 2;
        if (j < NIT) load_stage(j % GNST, j);
        cp_commit();
    }

    const int ep = args.epi[z];
    const float* bias = args.bias[z];
    float* Cg = args.C[z];
    const int ldc = args.ldc[z];
    const float* ex  = args.ex;
    const float* exx = args.exx;

    auto apply2 = [&](float& v0, float& v1, int row, int col) {
        if (ep == EPI_TANH) { v0 = tanhf(v0); v1 = tanhf(v1); }
        else if (ep == EPI_SILU) {
            v0 = v0 / (1.0f + expf(-v0));
            v1 = v1 / (1.0f + expf(-v1));
        } else if (ep == EPI_BIAS) { v0 += bias[col]; v1 += bias[col + 1]; }
        else if (ep == EPI_MIX) {
            size_t idx = (size_t)row * 1024 + col;
            float2 e  = *reinterpret_cast<const float2*>(ex  + idx);
            float2 dx = *reinterpret_cast<const float2*>(exx + idx);
            v0 = e.x + dx.x * (bias[col]     + v0);
            v1 = e.y + dx.y * (bias[col + 1] + v1);
        }
    };

#pragma unroll
    for (int mt = 0; mt < 4; mt++) {
        const int r0 = m0 + wm * 64 + mt * 16 + gid;
#pragma unroll
        for (int nt = 0; nt < 4; nt++) {
            const int col = n0 + wn * 32 + nt * 8 + tig * 2;
            if (col < Nz) {
                float v0 = c[mt][nt][0], v1 = c[mt][nt][1];
                apply2(v0, v1, r0, col);
                *reinterpret_cast<float2*>(Cg + (size_t)r0 * ldc + col)
                    = make_float2(v0, v1);
                float v2 = c[mt][nt][2], v3 = c[mt][nt][3];
                apply2(v2, v3, r0 + 8, col);
                *reinterpret_cast<float2*>(Cg + (size_t)(r0 + 8) * ldc + col)
                    = make_float2(v2, v3);
            }
        }
    }
}

// ------------------- batched fp32 transposes -------------------------------
struct TBatch {
    const float* src[8];
    float*       dst[8];
    int R[8], C[8];
};

__global__ void transpose_batch_kernel(const TBatch jobs)
{
    __shared__ float tile[32][33];
    const int z = blockIdx.z;
    const int bx = blockIdx.x * 32, by = blockIdx.y * 32;
    const int R = jobs.R[z], C = jobs.C[z];
    if (bx >= C || by >= R) return;
    const float* src = jobs.src[z];
    float*       dst = jobs.dst[z];
    const int tx = threadIdx.x, ty = threadIdx.y;   // (32, 8)
#pragma unroll
    for (int r = 0; r < 32; r += 8)
        tile[ty + r][tx] = src[(size_t)(by + ty + r) * C + bx + tx];
    __syncthreads();
#pragma unroll
    for (int r = 0; r < 32; r += 8)
        dst[(size_t)(bx + ty + r) * R + by + tx] = tile[tx][ty + r];
}

// ------------------------- elementwise: token shift ------------------------
__global__ void shift_kernel(const float* __restrict__ x,
                             const float* __restrict__ maa_x,
                             float* __restrict__ xx,
                             float* __restrict__ xxx)
{
    int i = blockIdx.x * blockDim.x + threadIdx.x;
    if (i >= MT * Cc) return;
    int c = i & (Cc - 1);
    int t = (i >> 10) & (Tc - 1);
    float xv = x[i];
    float xp = (t != 0) ? x[i - Cc] : 0.0f;
    float d  = xp - xv;
    xx[i]  = d;
    xxx[i] = xv + d * maa_x[c];
}

// ==================== chunked WKV6 (3 passes) ==============================
__global__ __launch_bounds__(64)
void wkv6_pass1_kernel(const float* __restrict__ k, const float* __restrict__ v,
                       float* __restrict__ w, float* __restrict__ sc,
                       float* __restrict__ dp)
{
    const int bh = blockIdx.x >> 4;
    const int c  = blockIdx.x & 15;
    const int b  = bh >> 4;
    const int h  = bh & 15;
    const int j  = threadIdx.x;
    const size_t base = (size_t)b * Tc * Cc + h * Kk + j;

    float S[64];
#pragma unroll
    for (int i = 0; i < 64; i++) S[i] = 0.0f;
    float Dj = 1.0f;

    __shared__ float2 q[64];

    const int t0 = c * CLEN;
    for (int t = t0; t < t0 + CLEN; t++) {
        const size_t off = base + (size_t)t * Cc;
        float kj = k[off];
        float vj = v[off];
        float wj = w[off];
        float wd = expf(-expf(wj));
        w[off] = wd;
        Dj *= wd;
        q[j] = make_float2(kj, wd);
        __syncthreads();
#pragma unroll
        for (int i = 0; i < 64; i += 4) {
            float2 q0 = q[i + 0], q1 = q[i + 1], q2 = q[i + 2], q3 = q[i + 3];
            S[i + 0] = fmaf(S[i + 0], q0.y, q0.x * vj);
            S[i + 1] = fmaf(S[i + 1], q1.y, q1.x * vj);
            S[i + 2] = fmaf(S[i + 2], q2.y, q2.x * vj);
            S[i + 3] = fmaf(S[i + 3], q3.y, q3.x * vj);
        }
        __syncthreads();
    }

    float* scp = sc + ((size_t)bh * NCHUNK + c) * (Kk * Kk);
#pragma unroll 8
    for (int i = 0; i < 64; i++) scp[i * 64 + j] = S[i];
    dp[((size_t)bh * NCHUNK + c) * Kk + j] = Dj;
}

__global__ __launch_bounds__(64)
void wkv6_pass2_kernel(float* __restrict__ sc, const float* __restrict__ dp)
{
    const int bh = blockIdx.x;
    const int j  = threadIdx.x;

    float R[64];
#pragma unroll
    for (int i = 0; i < 64; i++) R[i] = 0.0f;

    __shared__ float Ds[64];

    for (int c = 0; c < NCHUNK; c++) {
        Ds[j] = dp[((size_t)bh * NCHUNK + c) * Kk + j];
        __syncthreads();
        float* scp = sc + ((size_t)bh * NCHUNK + c) * (Kk * Kk);
#pragma unroll 4
        for (int i = 0; i < 64; i++) {
            float sl = scp[i * 64 + j];
            scp[i * 64 + j] = R[i];
            R[i] = fmaf(R[i], Ds[i], sl);
        }
        __syncthreads();
    }
}

__global__ __launch_bounds__(64)
void wkv6_pass3_kernel(const float* __restrict__ r, const float* __restrict__ k,
                       const float* __restrict__ v, const float* __restrict__ wd,
                       const float* __restrict__ u, const float* __restrict__ sc,
                       float* __restrict__ y)
{
    const int bh = blockIdx.x >> 4;
    const int c  = blockIdx.x & 15;
    const int b  = bh >> 4;
    const int h  = bh & 15;
    const int j  = threadIdx.x;
    const size_t base = (size_t)b * Tc * Cc + h * Kk + j;
    const float  uj   = u[h * Kk + j];

    float S[64];
    const float* scp = sc + ((size_t)bh * NCHUNK + c) * (Kk * Kk);
#pragma unroll 8
    for (int i = 0; i < 64; i++) S[i] = scp[i * 64 + j];

    __shared__ float4 q[64];

    const int t0 = c * CLEN;
    for (int t = t0; t < t0 + CLEN; t++) {
        const size_t off = base + (size_t)t * Cc;
        float rj = r[off];
        float kj = k[off];
        float dj = wd[off];
        float vj = v[off];
        q[j] = make_float4(rj, kj, dj, uj);
        __syncthreads();

        float y0 = 0.f, y1 = 0.f, y2 = 0.f, y3 = 0.f;
#pragma unroll
        for (int kk = 0; kk < 64; kk += 4) {
            float4 q0 = q[kk + 0];
            float4 q1 = q[kk + 1];
            float4 q2 = q[kk + 2];
            float4 q3 = q[kk + 3];
            float kv0 = q0.y * vj;
            float kv1 = q1.y * vj;
            float kv2 = q2.y * vj;
            float kv3 = q3.y * vj;
            y0 = fmaf(q0.x, fmaf(q0.w, kv0, S[kk + 0]), y0);
            y1 = fmaf(q1.x, fmaf(q1.w, kv1, S[kk + 1]), y1);
            y2 = fmaf(q2.x, fmaf(q2.w, kv2, S[kk + 2]), y2);
            y3 = fmaf(q3.x, fmaf(q3.w, kv3, S[kk + 3]), y3);
            S[kk + 0] = fmaf(S[kk + 0], q0.z, kv0);
            S[kk + 1] = fmaf(S[kk + 1], q1.z, kv1);
            S[kk + 2] = fmaf(S[kk + 2], q2.z, kv2);
            S[kk + 3] = fmaf(S[kk + 3], q3.z, kv3);
        }
        y[off] = (y0 + y1) + (y2 + y3);
        __syncthreads();
    }
}

// ------------------------- groupnorm + gate --------------------------------
__global__ __launch_bounds__(256)
void gnorm_kernel(const float* __restrict__ y, const float* __restrict__ gate,
                  const float* __restrict__ gamma, const float* __restrict__ beta,
                  float* __restrict__ z)
{
    const int row = blockIdx.x;
    const int tid = threadIdx.x;
    const int c0  = tid * 4;
    const size_t idx = (size_t)row * Cc + c0;

    float4 yv = *reinterpret_cast<const float4*>(y + idx);
    float s  = yv.x + yv.y + yv.z + yv.w;
    float ss = yv.x * yv.x + yv.y * yv.y + yv.z * yv.z + yv.w * yv.w;
#pragma unroll
    for (int o = 8; o > 0; o >>= 1) {
        s  += __shfl_xor_sync(0xffffffffu, s,  o);
        ss += __shfl_xor_sync(0xffffffffu, ss, o);
    }
    const float mean = s * (1.0f / 64.0f);
    const float var  = ss * (1.0f / 64.0f) - mean * mean;
    const float rstd = rsqrtf(var + EPSC);

    float4 gm = *reinterpret_cast<const float4*>(gamma + c0);
    float4 bt = *reinterpret_cast<const float4*>(beta + c0);
    float4 gt = *reinterpret_cast<const float4*>(gate + idx);
    float4 o;
    o.x = ((yv.x - mean) * rstd * gm.x + bt.x) * gt.x;
    o.y = ((yv.y - mean) * rstd * gm.y + bt.y) * gt.y;
    o.z = ((yv.z - mean) * rstd * gm.z + bt.z) * gt.z;
    o.w = ((yv.w - mean) * rstd * gm.w + bt.w) * gt.w;
    *reinterpret_cast<float4*>(z + idx) = o;
}

// ---------------------------------------------------------------------------
extern "C" void kernel_launch(void* const* d_in, const int* in_sizes, int n_in,
                              void* d_out, int out_size)
{
    const float* x      = (const float*)d_in[0];
    const float* maa_x  = (const float*)d_in[1];
    const float* maa_w  = (const float*)d_in[2];
    const float* maa_k  = (const float*)d_in[3];
    const float* maa_v  = (const float*)d_in[4];
    const float* maa_r  = (const float*)d_in[5];
    const float* maa_g  = (const float*)d_in[6];
    const float* maa_w1 = (const float*)d_in[7];
    const float* maa_w2 = (const float*)d_in[8];
    const float* tdecay = (const float*)d_in[9];
    const float* dw1    = (const float*)d_in[10];
    const float* dw2    = (const float*)d_in[11];
    const float* u      = (const float*)d_in[12];
    const float* W_r    = (const float*)d_in[13];
    const float* W_k    = (const float*)d_in[14];
    const float* W_v    = (const float*)d_in[15];
    const float* W_g    = (const float*)d_in[16];
    const float* W_o    = (const float*)d_in[17];
    const float* gamma  = (const float*)d_in[18];
    const float* beta   = (const float*)d_in[19];
    float* out = (float*)d_out;

    float *xx, *xxx, *m, *xw, *xk, *xv, *xr, *xg;
    float *rr, *kk, *vv, *gg, *ww, *t64, *y, *z;
    float *wt5, *w1t, *w2t, *dw1t, *dw2t, *sc, *dpp;
    cudaGetSymbolAddress((void**)&xx,   g_xx);
    cudaGetSymbolAddress((void**)&xxx,  g_xxx);
    cudaGetSymbolAddress((void**)&m,    g_m);
    cudaGetSymbolAddress((void**)&xw,   g_xw);
    cudaGetSymbolAddress((void**)&xk,   g_xk);
    cudaGetSymbolAddress((void**)&xv,   g_xv);
    cudaGetSymbolAddress((void**)&xr,   g_xr);
    cudaGetSymbolAddress((void**)&xg,   g_xg);
    cudaGetSymbolAddress((void**)&rr,   g_r);
    cudaGetSymbolAddress((void**)&kk,   g_k);
    cudaGetSymbolAddress((void**)&vv,   g_v);
    cudaGetSymbolAddress((void**)&gg,   g_g);
    cudaGetSymbolAddress((void**)&ww,   g_w);
    cudaGetSymbolAddress((void**)&t64,  g_t64);
    cudaGetSymbolAddress((void**)&y,    g_y);
    cudaGetSymbolAddress((void**)&z,    g_z);
    cudaGetSymbolAddress((void**)&wt5,  g_wt5);
    cudaGetSymbolAddress((void**)&w1t,  g_w1t);
    cudaGetSymbolAddress((void**)&w2t,  g_w2t);
    cudaGetSymbolAddress((void**)&dw1t, g_dw1t);
    cudaGetSymbolAddress((void**)&dw2t, g_dw2t);
    cudaGetSymbolAddress((void**)&sc,   g_sc);
    cudaGetSymbolAddress((void**)&dpp,  g_dp);

    cudaFuncSetAttribute(gemm_mma_kernel,
                         cudaFuncAttributeMaxDynamicSharedMemorySize, GSMEM_BYTES);

    const size_t WSZ = (size_t)Cc * Cc;
    dim3 tb(32, 8);

    // 0a) big weight transposes, one launch (z = 5 jobs, all 1024x1024)
    {
        TBatch j = {};
        const float* s5[5] = {W_r, W_k, W_v, W_g, W_o};
        for (int f = 0; f < 5; f++) {
            j.src[f] = s5[f]; j.dst[f] = wt5 + (size_t)f * WSZ;
            j.R[f] = 1024; j.C[f] = 1024;
        }
        for (int f = 5; f < 8; f++) { j.src[f] = W_r; j.dst[f] = wt5; j.R[f] = 0; j.C[f] = 0; }
        transpose_batch_kernel<<<dim3(32, 32, 5), tb>>>(j);
    }
    // 0b) small transposes, one launch (8 jobs, bounds-checked)
    {
        TBatch j = {};
        j.src[0] = maa_w1; j.dst[0] = w1t;  j.R[0] = 1024; j.C[0] = 160;
        for (int f = 0; f < 5; f++) {
            j.src[1 + f] = maa_w2 + (size_t)f * 32 * 1024;
            j.dst[1 + f] = w2t + (size_t)f * 1024 * 32;
            j.R[1 + f] = 32; j.C[1 + f] = 1024;
        }
        j.src[6] = dw1; j.dst[6] = dw1t; j.R[6] = 1024; j.C[6] = 64;
        j.src[7] = dw2; j.dst[7] = dw2t; j.R[7] = 64;   j.C[7] = 1024;
        transpose_batch_kernel<<<dim3(32, 32, 8), tb>>>(j);
    }

    // 1) token shift  (launch #3)
    shift_kernel<<<(MT * Cc + 255) / 256, 256>>>(x, maa_x, xx, xxx);

    // 2) m = tanh(xxx @ W1)   (launch #4)
    {
        GemmBatch a = {};
        a.A[0] = xxx; a.B[0] = w1t; a.C[0] = m;
        a.N[0] = 160; a.ldc[0] = 160; a.epi[0] = EPI_TANH;
        a.K = 1024; a.lda = 1024; a.ldb = 1024;
        gemm_mma_kernel<<<dim3(2, 32, 1), 256, GSMEM_BYTES>>>(a);
    }

    // 3) five mixing GEMMs  (launch #5)
    {
        GemmBatch a = {};
        const float* bias5[5] = {maa_w, maa_k, maa_v, maa_r, maa_g};
        float*       out5[5]  = {xw, xk, xv, xr, xg};
        for (int f = 0; f < 5; f++) {
            a.A[f] = m + f * 32;
            a.B[f] = w2t + (size_t)f * 1024 * 32;
            a.C[f] = out5[f];
            a.bias[f] = bias5[f];
            a.N[f] = 1024; a.ldc[f] = 1024; a.epi[f] = EPI_MIX;
        }
        a.ex = x; a.exx = xx;
        a.K = 32; a.lda = 160; a.ldb = 32;
        gemm_mma_kernel<<<dim3(8, 32, 5), 256, GSMEM_BYTES>>>(a);
    }

    // 4) projections r/k/v/g + decay LoRA-1  (launch #6 -> ncu captures this)
    {
        GemmBatch a = {};
        const float* As[5] = {xr, xk, xv, xg, xw};
        const float* Bs[5] = {wt5 + 0 * WSZ, wt5 + 1 * WSZ, wt5 + 2 * WSZ,
                              wt5 + 3 * WSZ, dw1t};
        float* Cs[5] = {rr, kk, vv, gg, t64};
        int Ns[5]   = {1024, 1024, 1024, 1024, 64};
        int ldcs[5] = {1024, 1024, 1024, 1024, 64};
        int epis[5] = {EPI_NONE, EPI_NONE, EPI_NONE, EPI_SILU, EPI_TANH};
        for (int f = 0; f < 5; f++) {
            a.A[f] = As[f]; a.B[f] = Bs[f]; a.C[f] = Cs[f];
            a.N[f] = Ns[f]; a.ldc[f] = ldcs[f]; a.epi[f] = epis[f];
        }
        a.K = 1024; a.lda = 1024; a.ldb = 1024;
        gemm_mma_kernel<<<dim3(8, 32, 5), 256, GSMEM_BYTES>>>(a);
    }

    // 5) decay LoRA-2: w = time_decay + t64 @ dw2
    {
        GemmBatch a = {};
        a.A[0] = t64; a.B[0] = dw2t; a.C[0] = ww; a.bias[0] = tdecay;
        a.N[0] = 1024; a.ldc[0] = 1024; a.epi[0] = EPI_BIAS;
        a.K = 64; a.lda = 64; a.ldb = 64;
        gemm_mma_kernel<<<dim3(8, 32, 1), 256, GSMEM_BYTES>>>(a);
    }

    // 6) chunked WKV6 scan (3 passes)
    wkv6_pass1_kernel<<<64 * NCHUNK, 64>>>(kk, vv, ww, sc, dpp);
    wkv6_pass2_kernel<<<64, 64>>>(sc, dpp);
    wkv6_pass3_kernel<<<64 * NCHUNK, 64>>>(rr, kk, vv, ww, u, sc, y);

    // 7) groupnorm + gate
    gnorm_kernel<<<MT, 256>>>(y, gg, gamma, beta, z);

    // 8) output projection
    {
        GemmBatch a = {};
        a.A[0] = z; a.B[0] = wt5 + 4 * WSZ; a.C[0] = out;
        a.N[0] = 1024; a.ldc[0] = 1024; a.epi[0] = EPI_NONE;
        a.K = 1024; a.lda = 1024; a.ldb = 1024;
        gemm_mma_kernel<<<dim3(8, 32, 1), 256, GSMEM_BYTES>>>(a);
    }
}

// round 11
// speedup vs baseline: 2.2679x; 1.1245x over previous
#include <cuda_runtime.h>
#include <math.h>
#include <stdint.h>

// ---------------------------------------------------------------------------
// RWKV v6 TimeMix  (B=4, T=1024, C=1024, H=16, K=64)
// Round 11: issue-bound GEMM mainloop slimmed — raw-fp32-as-tf32 hi operand
// (HW truncates low 13 bits) + LOP3/FSUB lo; split-K=2 on the tanh LoRA GEMM.
// ---------------------------------------------------------------------------

#define Bc 4
#define Tc 1024
#define Cc 1024
#define Hh 16
#define Kk 64
#define MT (Bc * Tc)          // 4096 rows
#define EPSC (1e-5f * 64.0f)
#define NCHUNK 16
#define CLEN   64

// ------------------------- scratch (static device mem) ---------------------
__device__ float g_xx  [MT * Cc];
__device__ float g_xxx [MT * Cc];
__device__ float g_m   [MT * 160];
__device__ float g_ms0 [MT * 160];
__device__ float g_ms1 [MT * 160];
__device__ float g_xw  [MT * Cc];
__device__ float g_xk  [MT * Cc];
__device__ float g_xv  [MT * Cc];
__device__ float g_xr  [MT * Cc];
__device__ float g_xg  [MT * Cc];
__device__ float g_r   [MT * Cc];
__device__ float g_k   [MT * Cc];
__device__ float g_v   [MT * Cc];
__device__ float g_g   [MT * Cc];
__device__ float g_w   [MT * Cc];      // w in, overwritten with wd=exp(-exp(w))
__device__ float g_t64 [MT * 64];
__device__ float g_y   [MT * Cc];
__device__ float g_z   [MT * Cc];
__device__ float g_wt5 [5 * Cc * Cc];
__device__ float g_w1t [160 * Cc];
__device__ float g_w2t [5 * Cc * 32];
__device__ float g_dw1t[64 * Cc];
__device__ float g_dw2t[Cc * 64];
__device__ float g_sc  [64 * NCHUNK * Kk * Kk];
__device__ float g_dp  [64 * NCHUNK * Kk];

// ======================= 3xTF32 mma.sync GEMM ==============================
enum { EPI_NONE = 0, EPI_TANH = 1, EPI_SILU = 2, EPI_BIAS = 3, EPI_MIX = 4 };

struct GemmBatch {
    const float* A[5];
    const float* B[5];
    float*       C[5];
    const float* bias[5];
    int          N[5];
    int          ldc[5];
    int          epi[5];
    const float* ex;
    const float* exx;
    int K, lda, ldb;
};

#define GSTAGE_FLOATS 9216            // (128*36)*2 per stage
#define GSTAGE_BYTES  36864u
#define GNST          3
#define GSMEM_BYTES   (3u * GSTAGE_BYTES)   // 110592

__device__ __forceinline__ void cp16(uint32_t saddr, const void* gptr, int sz) {
    asm volatile("cp.async.cg.shared.global [%0], [%1], 16, %2;"
                 :: "r"(saddr), "l"(gptr), "r"(sz));
}
__device__ __forceinline__ void cp_commit() {
    asm volatile("cp.async.commit_group;" ::: "memory");
}
__device__ __forceinline__ void cp_wait1() {
    asm volatile("cp.async.wait_group 1;" ::: "memory");
}
__device__ __forceinline__ uint32_t smem_u32(const void* p) {
    uint32_t a;
    asm("{ .reg .u64 t; cvta.to.shared.u64 t, %1; cvt.u32.u64 %0, t; }"
        : "=r"(a) : "l"(p));
    return a;
}
// Cheap hi/lo split: tf32 mma HW reads only the top 19 bits of the b32
// operand, so the raw fp32 bits ARE the hi operand (implicit truncation).
// lo = v - truncate(v) is exact in fp32 (same exponent, low mantissa bits).
__device__ __forceinline__ void split2(float v, uint32_t& hi, uint32_t& lo) {
    uint32_t vb = __float_as_uint(v);
    hi = vb;
    float hif = __uint_as_float(vb & 0xFFFFE000u);
    lo = __float_as_uint(v - hif);
}
__device__ __forceinline__ void mma_tf32_16n8k8(float c[4],
    uint32_t a0, uint32_t a1, uint32_t a2, uint32_t a3, uint32_t b0, uint32_t b1)
{
    asm volatile(
        "mma.sync.aligned.m16n8k8.row.col.f32.tf32.tf32.f32 "
        "{%0,%1,%2,%3}, {%4,%5,%6,%7}, {%8,%9}, {%0,%1,%2,%3};"
        : "+f"(c[0]), "+f"(c[1]), "+f"(c[2]), "+f"(c[3])
        : "r"(a0), "r"(a1), "r"(a2), "r"(a3), "r"(b0), "r"(b1));
}

__global__ void __launch_bounds__(256, 2)
gemm_mma_kernel(const GemmBatch args)
{
    extern __shared__ float smem[];
    const int z  = blockIdx.z;
    const int Nz = args.N[z];
    const int n0 = blockIdx.x * 128;
    if (n0 >= Nz) return;
    const int m0 = blockIdx.y * 128;

    const int tid = threadIdx.x;
    const int wid = tid >> 5;
    const int lid = tid & 31;
    const int wm  = wid >> 2;
    const int wn  = wid & 3;
    const int gid = lid >> 2;
    const int tig = lid & 3;

    const float* Ag = args.A[z];
    const float* Bg = args.B[z];
    const int lda = args.lda, ldb = args.ldb, K = args.K;
    const int NIT = K >> 5;

    const int arow = tid >> 1;
    const int acol = (tid & 1) * 16;
    const uint32_t sbase = smem_u32(smem);
    const int brow_ok = (n0 + arow) < Nz;
    const int bsz = brow_ok ? 16 : 0;
    const float* gArow = Ag + (size_t)(m0 + arow) * lda + acol;
    const float* gBrow = Bg + (size_t)(brow_ok ? (n0 + arow) : 0) * ldb + acol;

    auto load_stage = [&](int stage, int kt) {
        const uint32_t sA = sbase + (uint32_t)stage * GSTAGE_BYTES
                          + (uint32_t)(arow * 36 + acol) * 4u;
        const uint32_t sB = sA + 18432u;
        const float* ga = gArow + kt * 32;
        const float* gb = gBrow + kt * 32;
#pragma unroll
        for (int i = 0; i < 4; i++) cp16(sA + i * 16u, ga + i * 4, 16);
#pragma unroll
        for (int i = 0; i < 4; i++) cp16(sB + i * 16u, gb + i * 4, bsz);
    };

    float c[4][4][4];
#pragma unroll
    for (int mt = 0; mt < 4; mt++)
#pragma unroll
        for (int nt = 0; nt < 4; nt++)
#pragma unroll
            for (int i = 0; i < 4; i++) c[mt][nt][i] = 0.0f;

#pragma unroll
    for (int p = 0; p < 2; p++) {
        if (p < NIT) load_stage(p, p);
        cp_commit();
    }

    for (int kt = 0; kt < NIT; kt++) {
        cp_wait1();
        __syncthreads();

        int st = kt % GNST;
        const float* As  = smem + st * GSTAGE_FLOATS;
        const float* Bs  = As + 4608;
        const int    am  = wm * 64 + gid;
        const int    bn  = wn * 32 + gid;

#pragma unroll
        for (int ks = 0; ks < 4; ks++) {
            const int k0 = ks * 8 + tig;
            uint32_t bh[4][2], bl[4][2];
#pragma unroll
            for (int nt = 0; nt < 4; nt++) {
                const float* bp = Bs + (bn + nt * 8) * 36 + k0;
                split2(bp[0], bh[nt][0], bl[nt][0]);
                split2(bp[4], bh[nt][1], bl[nt][1]);
            }
#pragma unroll
            for (int mt = 0; mt < 4; mt++) {
                const float* ap = As + (am + mt * 16) * 36 + k0;
                uint32_t ah[4], al[4];
                split2(ap[0],          ah[0], al[0]);
                split2(ap[8 * 36],     ah[1], al[1]);
                split2(ap[4],          ah[2], al[2]);
                split2(ap[8 * 36 + 4], ah[3], al[3]);
#pragma unroll
                for (int nt = 0; nt < 4; nt++) {
                    mma_tf32_16n8k8(c[mt][nt], ah[0], ah[1], ah[2], ah[3],
                                    bh[nt][0], bh[nt][1]);
                    mma_tf32_16n8k8(c[mt][nt], ah[0], ah[1], ah[2], ah[3],
                                    bl[nt][0], bl[nt][1]);
                    mma_tf32_16n8k8(c[mt][nt], al[0], al[1], al[2], al[3],
                                    bh[nt][0], bh[nt][1]);
                }
            }
        }
        __syncthreads();
        const int j = kt + 2;
        if (j < NIT) load_stage(j % GNST, j);
        cp_commit();
    }

    const int ep = args.epi[z];
    const float* bias = args.bias[z];
    float* Cg = args.C[z];
    const int ldc = args.ldc[z];
    const float* ex  = args.ex;
    const float* exx = args.exx;

    auto apply2 = [&](float& v0, float& v1, int row, int col) {
        if (ep == EPI_TANH) { v0 = tanhf(v0); v1 = tanhf(v1); }
        else if (ep == EPI_SILU) {
            v0 = v0 / (1.0f + expf(-v0));
            v1 = v1 / (1.0f + expf(-v1));
        } else if (ep == EPI_BIAS) { v0 += bias[col]; v1 += bias[col + 1]; }
        else if (ep == EPI_MIX) {
            size_t idx = (size_t)row * 1024 + col;
            float2 e  = *reinterpret_cast<const float2*>(ex  + idx);
            float2 dx = *reinterpret_cast<const float2*>(exx + idx);
            v0 = e.x + dx.x * (bias[col]     + v0);
            v1 = e.y + dx.y * (bias[col + 1] + v1);
        }
    };

#pragma unroll
    for (int mt = 0; mt < 4; mt++) {
        const int r0 = m0 + wm * 64 + mt * 16 + gid;
#pragma unroll
        for (int nt = 0; nt < 4; nt++) {
            const int col = n0 + wn * 32 + nt * 8 + tig * 2;
            if (col < Nz) {
                float v0 = c[mt][nt][0], v1 = c[mt][nt][1];
                apply2(v0, v1, r0, col);
                *reinterpret_cast<float2*>(Cg + (size_t)r0 * ldc + col)
                    = make_float2(v0, v1);
                float v2 = c[mt][nt][2], v3 = c[mt][nt][3];
                apply2(v2, v3, r0 + 8, col);
                *reinterpret_cast<float2*>(Cg + (size_t)(r0 + 8) * ldc + col)
                    = make_float2(v2, v3);
            }
        }
    }
}

// ------------------- batched fp32 transposes -------------------------------
struct TBatch {
    const float* src[8];
    float*       dst[8];
    int R[8], C[8];
};

__global__ void transpose_batch_kernel(const TBatch jobs)
{
    __shared__ float tile[32][33];
    const int z = blockIdx.z;
    const int bx = blockIdx.x * 32, by = blockIdx.y * 32;
    const int R = jobs.R[z], C = jobs.C[z];
    if (bx >= C || by >= R) return;
    const float* src = jobs.src[z];
    float*       dst = jobs.dst[z];
    const int tx = threadIdx.x, ty = threadIdx.y;
#pragma unroll
    for (int r = 0; r < 32; r += 8)
        tile[ty + r][tx] = src[(size_t)(by + ty + r) * C + bx + tx];
    __syncthreads();
#pragma unroll
    for (int r = 0; r < 32; r += 8)
        dst[(size_t)(bx + ty + r) * R + by + tx] = tile[tx][ty + r];
}

// ------------------------- elementwise: token shift ------------------------
__global__ void shift_kernel(const float* __restrict__ x,
                             const float* __restrict__ maa_x,
                             float* __restrict__ xx,
                             float* __restrict__ xxx)
{
    int i = blockIdx.x * blockDim.x + threadIdx.x;
    if (i >= MT * Cc) return;
    int c = i & (Cc - 1);
    int t = (i >> 10) & (Tc - 1);
    float xv = x[i];
    float xp = (t != 0) ? x[i - Cc] : 0.0f;
    float d  = xp - xv;
    xx[i]  = d;
    xxx[i] = xv + d * maa_x[c];
}

// split-K combine: m = tanh(a + b)
__global__ void tanh_combine_kernel(const float* __restrict__ a,
                                    const float* __restrict__ b,
                                    float* __restrict__ o, int n)
{
    int i = blockIdx.x * blockDim.x + threadIdx.x;
    if (i < n) o[i] = tanhf(a[i] + b[i]);
}

// ==================== chunked WKV6 (3 passes) ==============================
__global__ __launch_bounds__(64)
void wkv6_pass1_kernel(const float* __restrict__ k, const float* __restrict__ v,
                       float* __restrict__ w, float* __restrict__ sc,
                       float* __restrict__ dp)
{
    const int bh = blockIdx.x >> 4;
    const int c  = blockIdx.x & 15;
    const int b  = bh >> 4;
    const int h  = bh & 15;
    const int j  = threadIdx.x;
    const size_t base = (size_t)b * Tc * Cc + h * Kk + j;

    float S[64];
#pragma unroll
    for (int i = 0; i < 64; i++) S[i] = 0.0f;
    float Dj = 1.0f;

    __shared__ float2 q[64];

    const int t0 = c * CLEN;
    for (int t = t0; t < t0 + CLEN; t++) {
        const size_t off = base + (size_t)t * Cc;
        float kj = k[off];
        float vj = v[off];
        float wj = w[off];
        float wd = expf(-expf(wj));
        w[off] = wd;
        Dj *= wd;
        q[j] = make_float2(kj, wd);
        __syncthreads();
#pragma unroll
        for (int i = 0; i < 64; i += 4) {
            float2 q0 = q[i + 0], q1 = q[i + 1], q2 = q[i + 2], q3 = q[i + 3];
            S[i + 0] = fmaf(S[i + 0], q0.y, q0.x * vj);
            S[i + 1] = fmaf(S[i + 1], q1.y, q1.x * vj);
            S[i + 2] = fmaf(S[i + 2], q2.y, q2.x * vj);
            S[i + 3] = fmaf(S[i + 3], q3.y, q3.x * vj);
        }
        __syncthreads();
    }

    float* scp = sc + ((size_t)bh * NCHUNK + c) * (Kk * Kk);
#pragma unroll 8
    for (int i = 0; i < 64; i++) scp[i * 64 + j] = S[i];
    dp[((size_t)bh * NCHUNK + c) * Kk + j] = Dj;
}

__global__ __launch_bounds__(64)
void wkv6_pass2_kernel(float* __restrict__ sc, const float* __restrict__ dp)
{
    const int bh = blockIdx.x;
    const int j  = threadIdx.x;

    float R[64];
#pragma unroll
    for (int i = 0; i < 64; i++) R[i] = 0.0f;

    __shared__ float Ds[64];

    for (int c = 0; c < NCHUNK; c++) {
        Ds[j] = dp[((size_t)bh * NCHUNK + c) * Kk + j];
        __syncthreads();
        float* scp = sc + ((size_t)bh * NCHUNK + c) * (Kk * Kk);
#pragma unroll 4
        for (int i = 0; i < 64; i++) {
            float sl = scp[i * 64 + j];
            scp[i * 64 + j] = R[i];
            R[i] = fmaf(R[i], Ds[i], sl);
        }
        __syncthreads();
    }
}

__global__ __launch_bounds__(64)
void wkv6_pass3_kernel(const float* __restrict__ r, const float* __restrict__ k,
                       const float* __restrict__ v, const float* __restrict__ wd,
                       const float* __restrict__ u, const float* __restrict__ sc,
                       float* __restrict__ y)
{
    const int bh = blockIdx.x >> 4;
    const int c  = blockIdx.x & 15;
    const int b  = bh >> 4;
    const int h  = bh & 15;
    const int j  = threadIdx.x;
    const size_t base = (size_t)b * Tc * Cc + h * Kk + j;
    const float  uj   = u[h * Kk + j];

    float S[64];
    const float* scp = sc + ((size_t)bh * NCHUNK + c) * (Kk * Kk);
#pragma unroll 8
    for (int i = 0; i < 64; i++) S[i] = scp[i * 64 + j];

    __shared__ float4 q[64];

    const int t0 = c * CLEN;
    for (int t = t0; t < t0 + CLEN; t++) {
        const size_t off = base + (size_t)t * Cc;
        float rj = r[off];
        float kj = k[off];
        float dj = wd[off];
        float vj = v[off];
        q[j] = make_float4(rj, kj, dj, uj);
        __syncthreads();

        float y0 = 0.f, y1 = 0.f, y2 = 0.f, y3 = 0.f;
#pragma unroll
        for (int kk = 0; kk < 64; kk += 4) {
            float4 q0 = q[kk + 0];
            float4 q1 = q[kk + 1];
            float4 q2 = q[kk + 2];
            float4 q3 = q[kk + 3];
            float kv0 = q0.y * vj;
            float kv1 = q1.y * vj;
            float kv2 = q2.y * vj;
            float kv3 = q3.y * vj;
            y0 = fmaf(q0.x, fmaf(q0.w, kv0, S[kk + 0]), y0);
            y1 = fmaf(q1.x, fmaf(q1.w, kv1, S[kk + 1]), y1);
            y2 = fmaf(q2.x, fmaf(q2.w, kv2, S[kk + 2]), y2);
            y3 = fmaf(q3.x, fmaf(q3.w, kv3, S[kk + 3]), y3);
            S[kk + 0] = fmaf(S[kk + 0], q0.z, kv0);
            S[kk + 1] = fmaf(S[kk + 1], q1.z, kv1);
            S[kk + 2] = fmaf(S[kk + 2], q2.z, kv2);
            S[kk + 3] = fmaf(S[kk + 3], q3.z, kv3);
        }
        y[off] = (y0 + y1) + (y2 + y3);
        __syncthreads();
    }
}

// ------------------------- groupnorm + gate --------------------------------
__global__ __launch_bounds__(256)
void gnorm_kernel(const float* __restrict__ y, const float* __restrict__ gate,
                  const float* __restrict__ gamma, const float* __restrict__ beta,
                  float* __restrict__ z)
{
    const int row = blockIdx.x;
    const int tid = threadIdx.x;
    const int c0  = tid * 4;
    const size_t idx = (size_t)row * Cc + c0;

    float4 yv = *reinterpret_cast<const float4*>(y + idx);
    float s  = yv.x + yv.y + yv.z + yv.w;
    float ss = yv.x * yv.x + yv.y * yv.y + yv.z * yv.z + yv.w * yv.w;
#pragma unroll
    for (int o = 8; o > 0; o >>= 1) {
        s  += __shfl_xor_sync(0xffffffffu, s,  o);
        ss += __shfl_xor_sync(0xffffffffu, ss, o);
    }
    const float mean = s * (1.0f / 64.0f);
    const float var  = ss * (1.0f / 64.0f) - mean * mean;
    const float rstd = rsqrtf(var + EPSC);

    float4 gm = *reinterpret_cast<const float4*>(gamma + c0);
    float4 bt = *reinterpret_cast<const float4*>(beta + c0);
    float4 gt = *reinterpret_cast<const float4*>(gate + idx);
    float4 o;
    o.x = ((yv.x - mean) * rstd * gm.x + bt.x) * gt.x;
    o.y = ((yv.y - mean) * rstd * gm.y + bt.y) * gt.y;
    o.z = ((yv.z - mean) * rstd * gm.z + bt.z) * gt.z;
    o.w = ((yv.w - mean) * rstd * gm.w + bt.w) * gt.w;
    *reinterpret_cast<float4*>(z + idx) = o;
}

// ---------------------------------------------------------------------------
extern "C" void kernel_launch(void* const* d_in, const int* in_sizes, int n_in,
                              void* d_out, int out_size)
{
    const float* x      = (const float*)d_in[0];
    const float* maa_x  = (const float*)d_in[1];
    const float* maa_w  = (const float*)d_in[2];
    const float* maa_k  = (const float*)d_in[3];
    const float* maa_v  = (const float*)d_in[4];
    const float* maa_r  = (const float*)d_in[5];
    const float* maa_g  = (const float*)d_in[6];
    const float* maa_w1 = (const float*)d_in[7];
    const float* maa_w2 = (const float*)d_in[8];
    const float* tdecay = (const float*)d_in[9];
    const float* dw1    = (const float*)d_in[10];
    const float* dw2    = (const float*)d_in[11];
    const float* u      = (const float*)d_in[12];
    const float* W_r    = (const float*)d_in[13];
    const float* W_k    = (const float*)d_in[14];
    const float* W_v    = (const float*)d_in[15];
    const float* W_g    = (const float*)d_in[16];
    const float* W_o    = (const float*)d_in[17];
    const float* gamma  = (const float*)d_in[18];
    const float* beta   = (const float*)d_in[19];
    float* out = (float*)d_out;

    float *xx, *xxx, *m, *ms0, *ms1, *xw, *xk, *xv, *xr, *xg;
    float *rr, *kk, *vv, *gg, *ww, *t64, *y, *z;
    float *wt5, *w1t, *w2t, *dw1t, *dw2t, *sc, *dpp;
    cudaGetSymbolAddress((void**)&xx,   g_xx);
    cudaGetSymbolAddress((void**)&xxx,  g_xxx);
    cudaGetSymbolAddress((void**)&m,    g_m);
    cudaGetSymbolAddress((void**)&ms0,  g_ms0);
    cudaGetSymbolAddress((void**)&ms1,  g_ms1);
    cudaGetSymbolAddress((void**)&xw,   g_xw);
    cudaGetSymbolAddress((void**)&xk,   g_xk);
    cudaGetSymbolAddress((void**)&xv,   g_xv);
    cudaGetSymbolAddress((void**)&xr,   g_xr);
    cudaGetSymbolAddress((void**)&xg,   g_xg);
    cudaGetSymbolAddress((void**)&rr,   g_r);
    cudaGetSymbolAddress((void**)&kk,   g_k);
    cudaGetSymbolAddress((void**)&vv,   g_v);
    cudaGetSymbolAddress((void**)&gg,   g_g);
    cudaGetSymbolAddress((void**)&ww,   g_w);
    cudaGetSymbolAddress((void**)&t64,  g_t64);
    cudaGetSymbolAddress((void**)&y,    g_y);
    cudaGetSymbolAddress((void**)&z,    g_z);
    cudaGetSymbolAddress((void**)&wt5,  g_wt5);
    cudaGetSymbolAddress((void**)&w1t,  g_w1t);
    cudaGetSymbolAddress((void**)&w2t,  g_w2t);
    cudaGetSymbolAddress((void**)&dw1t, g_dw1t);
    cudaGetSymbolAddress((void**)&dw2t, g_dw2t);
    cudaGetSymbolAddress((void**)&sc,   g_sc);
    cudaGetSymbolAddress((void**)&dpp,  g_dp);

    cudaFuncSetAttribute(gemm_mma_kernel,
                         cudaFuncAttributeMaxDynamicSharedMemorySize, GSMEM_BYTES);

    const size_t WSZ = (size_t)Cc * Cc;
    dim3 tb(32, 8);

    // 0a) big weight transposes
    {
        TBatch j = {};
        const float* s5[5] = {W_r, W_k, W_v, W_g, W_o};
        for (int f = 0; f < 5; f++) {
            j.src[f] = s5[f]; j.dst[f] = wt5 + (size_t)f * WSZ;
            j.R[f] = 1024; j.C[f] = 1024;
        }
        for (int f = 5; f < 8; f++) { j.src[f] = W_r; j.dst[f] = wt5; j.R[f] = 0; j.C[f] = 0; }
        transpose_batch_kernel<<<dim3(32, 32, 5), tb>>>(j);
    }
    // 0b) small transposes
    {
        TBatch j = {};
        j.src[0] = maa_w1; j.dst[0] = w1t;  j.R[0] = 1024; j.C[0] = 160;
        for (int f = 0; f < 5; f++) {
            j.src[1 + f] = maa_w2 + (size_t)f * 32 * 1024;
            j.dst[1 + f] = w2t + (size_t)f * 1024 * 32;
            j.R[1 + f] = 32; j.C[1 + f] = 1024;
        }
        j.src[6] = dw1; j.dst[6] = dw1t; j.R[6] = 1024; j.C[6] = 64;
        j.src[7] = dw2; j.dst[7] = dw2t; j.R[7] = 64;   j.C[7] = 1024;
        transpose_batch_kernel<<<dim3(32, 32, 8), tb>>>(j);
    }

    // 1) token shift
    shift_kernel<<<(MT * Cc + 255) / 256, 256>>>(x, maa_x, xx, xxx);

    // 2) m = tanh(xxx @ W1), split-K=2  [4096 x 160 x 512] x2, then combine
    {
        GemmBatch a = {};
        a.A[0] = xxx;       a.B[0] = w1t;       a.C[0] = ms0;
        a.A[1] = xxx + 512; a.B[1] = w1t + 512; a.C[1] = ms1;
        a.N[0] = a.N[1] = 160; a.ldc[0] = a.ldc[1] = 160;
        a.epi[0] = a.epi[1] = EPI_NONE;
        a.K = 512; a.lda = 1024; a.ldb = 1024;
        gemm_mma_kernel<<<dim3(2, 32, 2), 256, GSMEM_BYTES>>>(a);
        tanh_combine_kernel<<<(MT * 160 + 255) / 256, 256>>>(ms0, ms1, m, MT * 160);
    }

    // 3) five mixing GEMMs  [4096 x 1024 x 32] x5
    {
        GemmBatch a = {};
        const float* bias5[5] = {maa_w, maa_k, maa_v, maa_r, maa_g};
        float*       out5[5]  = {xw, xk, xv, xr, xg};
        for (int f = 0; f < 5; f++) {
            a.A[f] = m + f * 32;
            a.B[f] = w2t + (size_t)f * 1024 * 32;
            a.C[f] = out5[f];
            a.bias[f] = bias5[f];
            a.N[f] = 1024; a.ldc[f] = 1024; a.epi[f] = EPI_MIX;
        }
        a.ex = x; a.exx = xx;
        a.K = 32; a.lda = 160; a.ldb = 32;
        gemm_mma_kernel<<<dim3(8, 32, 5), 256, GSMEM_BYTES>>>(a);
    }

    // 4) projections r/k/v/g + decay LoRA-1, batched  (K=1024)
    {
        GemmBatch a = {};
        const float* As[5] = {xr, xk, xv, xg, xw};
        const float* Bs[5] = {wt5 + 0 * WSZ, wt5 + 1 * WSZ, wt5 + 2 * WSZ,
                              wt5 + 3 * WSZ, dw1t};
        float* Cs[5] = {rr, kk, vv, gg, t64};
        int Ns[5]   = {1024, 1024, 1024, 1024, 64};
        int ldcs[5] = {1024, 1024, 1024, 1024, 64};
        int epis[5] = {EPI_NONE, EPI_NONE, EPI_NONE, EPI_SILU, EPI_TANH};
        for (int f = 0; f < 5; f++) {
            a.A[f] = As[f]; a.B[f] = Bs[f]; a.C[f] = Cs[f];
            a.N[f] = Ns[f]; a.ldc[f] = ldcs[f]; a.epi[f] = epis[f];
        }
        a.K = 1024; a.lda = 1024; a.ldb = 1024;
        gemm_mma_kernel<<<dim3(8, 32, 5), 256, GSMEM_BYTES>>>(a);
    }

    // 5) decay LoRA-2: w = time_decay + t64 @ dw2
    {
        GemmBatch a = {};
        a.A[0] = t64; a.B[0] = dw2t; a.C[0] = ww; a.bias[0] = tdecay;
        a.N[0] = 1024; a.ldc[0] = 1024; a.epi[0] = EPI_BIAS;
        a.K = 64; a.lda = 64; a.ldb = 64;
        gemm_mma_kernel<<<dim3(8, 32, 1), 256, GSMEM_BYTES>>>(a);
    }

    // 6) chunked WKV6 scan (3 passes)
    wkv6_pass1_kernel<<<64 * NCHUNK, 64>>>(kk, vv, ww, sc, dpp);
    wkv6_pass2_kernel<<<64, 64>>>(sc, dpp);
    wkv6_pass3_kernel<<<64 * NCHUNK, 64>>>(rr, kk, vv, ww, u, sc, y);

    // 7) groupnorm + gate
    gnorm_kernel<<<MT, 256>>>(y, gg, gamma, beta, z);

    // 8) output projection
    {
        GemmBatch a = {};
        a.A[0] = z; a.B[0] = wt5 + 4 * WSZ; a.C[0] = out;
        a.N[0] = 1024; a.ldc[0] = 1024; a.epi[0] = EPI_NONE;
        a.K = 1024; a.lda = 1024; a.ldb = 1024;
        gemm_mma_kernel<<<dim3(8, 32, 1), 256, GSMEM_BYTES>>>(a);
    }
}

// round 14
// speedup vs baseline: 3.1145x; 1.3733x over previous
#include <cuda_runtime.h>
#include <cuda_bf16.h>
#include <math.h>
#include <stdint.h>

// ---------------------------------------------------------------------------
// RWKV v6 TimeMix  (B=4, T=1024, C=1024, H=16, K=64)
// Round 14 (resubmit of R13; container flake): bf16x3 emulated-fp32 GEMMs,
// ROWB=80 (16B-aligned cp.async dst), 2-stage pipeline @ 2 CTAs/SM.
// ---------------------------------------------------------------------------

#define Bc 4
#define Tc 1024
#define Cc 1024
#define Hh 16
#define Kk 64
#define MT (Bc * Tc)
#define EPSC (1e-5f * 64.0f)
#define NCHUNK 16
#define CLEN   64

typedef __nv_bfloat16 bf16;

// ------------------------- scratch (static device mem) ---------------------
__device__ float g_xx  [MT * Cc];
__device__ float g_ms0 [MT * 160];
__device__ float g_ms1 [MT * 160];
__device__ float g_r   [MT * Cc];
__device__ float g_k   [MT * Cc];
__device__ float g_v   [MT * Cc];
__device__ float g_g   [MT * Cc];
__device__ float g_w   [MT * Cc];
__device__ float g_y   [MT * Cc];
__device__ float g_sc  [64 * NCHUNK * Kk * Kk];
__device__ float g_dp  [64 * NCHUNK * Kk];
// bf16 hi/lo planes (256B-aligned for cp.async 16B global loads)
__device__ __align__(256) bf16 g_wt5h [5 * Cc * Cc];
__device__ __align__(256) bf16 g_wt5l [5 * Cc * Cc];
__device__ __align__(256) bf16 g_w1th [160 * Cc];
__device__ __align__(256) bf16 g_w1tl [160 * Cc];
__device__ __align__(256) bf16 g_w2th [5 * Cc * 32];
__device__ __align__(256) bf16 g_w2tl [5 * Cc * 32];
__device__ __align__(256) bf16 g_dw1th[64 * Cc];
__device__ __align__(256) bf16 g_dw1tl[64 * Cc];
__device__ __align__(256) bf16 g_dw2th[Cc * 64];
__device__ __align__(256) bf16 g_dw2tl[Cc * 64];
__device__ __align__(256) bf16 g_xxxh [MT * Cc];
__device__ __align__(256) bf16 g_xxxl [MT * Cc];
__device__ __align__(256) bf16 g_mh   [MT * 160];
__device__ __align__(256) bf16 g_ml   [MT * 160];
__device__ __align__(256) bf16 g_xwh  [MT * Cc];
__device__ __align__(256) bf16 g_xwl  [MT * Cc];
__device__ __align__(256) bf16 g_xkh  [MT * Cc];
__device__ __align__(256) bf16 g_xkl  [MT * Cc];
__device__ __align__(256) bf16 g_xvh  [MT * Cc];
__device__ __align__(256) bf16 g_xvl  [MT * Cc];
__device__ __align__(256) bf16 g_xrh  [MT * Cc];
__device__ __align__(256) bf16 g_xrl  [MT * Cc];
__device__ __align__(256) bf16 g_xgh  [MT * Cc];
__device__ __align__(256) bf16 g_xgl  [MT * Cc];
__device__ __align__(256) bf16 g_t64h [MT * 64];
__device__ __align__(256) bf16 g_t64l [MT * 64];
__device__ __align__(256) bf16 g_zh   [MT * Cc];
__device__ __align__(256) bf16 g_zl   [MT * Cc];

__device__ __forceinline__ void fsplit(float v, bf16& h, bf16& l) {
    h = __float2bfloat16(v);
    l = __float2bfloat16(v - __bfloat162float(h));
}

// ======================= bf16x3 mma.sync GEMM ==============================
enum { EPI_NONE = 0, EPI_TANH = 1, EPI_SILU = 2, EPI_BIAS = 3, EPI_MIX = 4 };

struct GemmBatch {
    const bf16* Ah[5]; const bf16* Al[5];
    const bf16* Bh[5]; const bf16* Bl[5];
    float*      C[5];
    bf16*       Ch[5]; bf16* Cl[5];
    const float* bias[5];
    int N[5], ldc[5], epi[5], pair[5];
    const float* ex; const float* exx;
    int K, lda, ldb;
};

// stage: 4 planes (Ah,Al,Bh,Bl), each 128 rows x 80B (32 bf16 = 64B + 16B pad)
#define ROWB       80u
#define PLANE_B    10240u               // 128*80
#define GSTAGE_B   40960u
#define GSMEM_BYTES (2u * GSTAGE_B)     // 81920 -> 2 CTAs/SM

__device__ __forceinline__ void cp16(uint32_t saddr, const void* gptr, int sz) {
    asm volatile("cp.async.cg.shared.global [%0], [%1], 16, %2;"
                 :: "r"(saddr), "l"(gptr), "r"(sz));
}
__device__ __forceinline__ void cp_commit() {
    asm volatile("cp.async.commit_group;" ::: "memory");
}
__device__ __forceinline__ void cp_wait1() {
    asm volatile("cp.async.wait_group 1;" ::: "memory");
}
__device__ __forceinline__ uint32_t smem_u32(const void* p) {
    uint32_t a;
    asm("{ .reg .u64 t; cvta.to.shared.u64 t, %1; cvt.u32.u64 %0, t; }"
        : "=r"(a) : "l"(p));
    return a;
}
__device__ __forceinline__ void mma_bf16(float c[4],
    uint32_t a0, uint32_t a1, uint32_t a2, uint32_t a3, uint32_t b0, uint32_t b1)
{
    asm volatile(
        "mma.sync.aligned.m16n8k16.row.col.f32.bf16.bf16.f32 "
        "{%0,%1,%2,%3}, {%4,%5,%6,%7}, {%8,%9}, {%0,%1,%2,%3};"
        : "+f"(c[0]), "+f"(c[1]), "+f"(c[2]), "+f"(c[3])
        : "r"(a0), "r"(a1), "r"(a2), "r"(a3), "r"(b0), "r"(b1));
}
__device__ __forceinline__ uint32_t lds32(const char* p) {
    return *reinterpret_cast<const uint32_t*>(p);
}

__global__ void __launch_bounds__(256, 2)
gemm_bf16x3_kernel(const GemmBatch args)
{
    extern __shared__ char smem[];
    const int z  = blockIdx.z;
    const int Nz = args.N[z];
    const int n0 = blockIdx.x * 128;
    if (n0 >= Nz) return;
    const int m0 = blockIdx.y * 128;

    const int tid = threadIdx.x;
    const int wid = tid >> 5;
    const int lid = tid & 31;
    const int wm  = wid >> 2;
    const int wn  = wid & 3;
    const int gid = lid >> 2;
    const int tig = lid & 3;

    const int lda = args.lda, ldb = args.ldb, K = args.K;
    const int NIT = K >> 5;

    const int arow = tid >> 1;
    const int side = tid & 1;            // 32B half of a 64B data row
    const uint32_t sbase = smem_u32(smem);
    const int brow_ok = (n0 + arow) < Nz;
    const int bsz = brow_ok ? 16 : 0;
    const int brow = brow_ok ? (n0 + arow) : 0;

    const bf16* gAh = args.Ah[z] + (size_t)(m0 + arow) * lda + side * 16;
    const bf16* gAl = args.Al[z] + (size_t)(m0 + arow) * lda + side * 16;
    const bf16* gBh = args.Bh[z] + (size_t)brow * ldb + side * 16;
    const bf16* gBl = args.Bl[z] + (size_t)brow * ldb + side * 16;

    auto load_stage = [&](int st, int kt) {
        const uint32_t rb = sbase + (uint32_t)st * GSTAGE_B
                          + (uint32_t)arow * ROWB + (uint32_t)side * 32u;
        const int ke = kt * 32;
        cp16(rb,                     gAh + ke,     16);
        cp16(rb + 16u,               gAh + ke + 8, 16);
        cp16(rb + PLANE_B,           gAl + ke,     16);
        cp16(rb + PLANE_B + 16u,     gAl + ke + 8, 16);
        cp16(rb + 2 * PLANE_B,       gBh + ke,     bsz);
        cp16(rb + 2 * PLANE_B + 16u, gBh + ke + 8, bsz);
        cp16(rb + 3 * PLANE_B,       gBl + ke,     bsz);
        cp16(rb + 3 * PLANE_B + 16u, gBl + ke + 8, bsz);
    };

    float c[4][4][4];
#pragma unroll
    for (int mt = 0; mt < 4; mt++)
#pragma unroll
        for (int nt = 0; nt < 4; nt++)
#pragma unroll
            for (int i = 0; i < 4; i++) c[mt][nt][i] = 0.0f;

    // 2-stage pipeline: prologue loads stage 0
    load_stage(0, 0);
    cp_commit();

    const int am = wm * 64 + gid;
    const int bn = wn * 32 + gid;

    for (int kt = 0; kt < NIT; kt++) {
        if (kt + 1 < NIT) load_stage((kt + 1) & 1, kt + 1);
        cp_commit();
        cp_wait1();          // all but newest group -> stage kt ready
        __syncthreads();

        const char* St  = smem + (kt & 1) * GSTAGE_B;
        const char* SAh = St;
        const char* SAl = St + PLANE_B;
        const char* SBh = St + 2 * PLANE_B;
        const char* SBl = St + 3 * PLANE_B;

#pragma unroll
        for (int ks = 0; ks < 2; ks++) {
            const uint32_t kb = (uint32_t)ks * 32u + (uint32_t)tig * 4u;
            uint32_t bh[4][2], bl[4][2];
#pragma unroll
            for (int nt = 0; nt < 4; nt++) {
                const uint32_t off = (uint32_t)(bn + nt * 8) * ROWB + kb;
                bh[nt][0] = lds32(SBh + off);
                bh[nt][1] = lds32(SBh + off + 16u);
                bl[nt][0] = lds32(SBl + off);
                bl[nt][1] = lds32(SBl + off + 16u);
            }
#pragma unroll
            for (int mt = 0; mt < 4; mt++) {
                const uint32_t ao = (uint32_t)(am + mt * 16) * ROWB + kb;
                uint32_t ah0 = lds32(SAh + ao);
                uint32_t ah1 = lds32(SAh + ao + 8u * ROWB);
                uint32_t ah2 = lds32(SAh + ao + 16u);
                uint32_t ah3 = lds32(SAh + ao + 8u * ROWB + 16u);
                uint32_t al0 = lds32(SAl + ao);
                uint32_t al1 = lds32(SAl + ao + 8u * ROWB);
                uint32_t al2 = lds32(SAl + ao + 16u);
                uint32_t al3 = lds32(SAl + ao + 8u * ROWB + 16u);
#pragma unroll
                for (int nt = 0; nt < 4; nt++) {
                    mma_bf16(c[mt][nt], ah0, ah1, ah2, ah3, bh[nt][0], bh[nt][1]);
                    mma_bf16(c[mt][nt], ah0, ah1, ah2, ah3, bl[nt][0], bl[nt][1]);
                    mma_bf16(c[mt][nt], al0, al1, al2, al3, bh[nt][0], bh[nt][1]);
                }
            }
        }
        __syncthreads();
    }

    // -------- epilogue --------
    const int ep   = args.epi[z];
    const int pair = args.pair[z];
    const float* bias = args.bias[z];
    const int ldc = args.ldc[z];
    float* Cg = args.C[z];
    bf16*  Chg = args.Ch[z];
    bf16*  Clg = args.Cl[z];
    const float* ex  = args.ex;
    const float* exx = args.exx;

    auto apply2 = [&](float& v0, float& v1, int row, int col) {
        if (ep == EPI_TANH) { v0 = tanhf(v0); v1 = tanhf(v1); }
        else if (ep == EPI_SILU) {
            v0 = v0 / (1.0f + expf(-v0));
            v1 = v1 / (1.0f + expf(-v1));
        } else if (ep == EPI_BIAS) { v0 += bias[col]; v1 += bias[col + 1]; }
        else if (ep == EPI_MIX) {
            size_t idx = (size_t)row * 1024 + col;
            float2 e  = *reinterpret_cast<const float2*>(ex  + idx);
            float2 dx = *reinterpret_cast<const float2*>(exx + idx);
            v0 = e.x + dx.x * (bias[col]     + v0);
            v1 = e.y + dx.y * (bias[col + 1] + v1);
        }
    };
    auto store2 = [&](float v0, float v1, int row, int col) {
        if (pair) {
            bf16 h0, l0, h1, l1;
            fsplit(v0, h0, l0);
            fsplit(v1, h1, l1);
            *reinterpret_cast<__nv_bfloat162*>(Chg + (size_t)row * ldc + col)
                = __nv_bfloat162(h0, h1);
            *reinterpret_cast<__nv_bfloat162*>(Clg + (size_t)row * ldc + col)
                = __nv_bfloat162(l0, l1);
        } else {
            *reinterpret_cast<float2*>(Cg + (size_t)row * ldc + col)
                = make_float2(v0, v1);
        }
    };

#pragma unroll
    for (int mt = 0; mt < 4; mt++) {
        const int r0 = m0 + wm * 64 + mt * 16 + gid;
#pragma unroll
        for (int nt = 0; nt < 4; nt++) {
            const int col = n0 + wn * 32 + nt * 8 + tig * 2;
            if (col < Nz) {
                float v0 = c[mt][nt][0], v1 = c[mt][nt][1];
                apply2(v0, v1, r0, col);
                store2(v0, v1, r0, col);
                float v2 = c[mt][nt][2], v3 = c[mt][nt][3];
                apply2(v2, v3, r0 + 8, col);
                store2(v2, v3, r0 + 8, col);
            }
        }
    }
}

// ------------------- batched transpose + bf16 split ------------------------
struct TBatch {
    const float* src[8];
    bf16* dsth[8]; bf16* dstl[8];
    int R[8], C[8];
};

__global__ void transpose_split_kernel(const TBatch jobs)
{
    __shared__ float tile[32][33];
    const int z = blockIdx.z;
    const int bx = blockIdx.x * 32, by = blockIdx.y * 32;
    const int R = jobs.R[z], C = jobs.C[z];
    if (bx >= C || by >= R) return;
    const float* src = jobs.src[z];
    bf16* dh = jobs.dsth[z];
    bf16* dl = jobs.dstl[z];
    const int tx = threadIdx.x, ty = threadIdx.y;
#pragma unroll
    for (int r = 0; r < 32; r += 8)
        tile[ty + r][tx] = src[(size_t)(by + ty + r) * C + bx + tx];
    __syncthreads();
#pragma unroll
    for (int r = 0; r < 32; r += 8) {
        float v = tile[tx][ty + r];
        bf16 h, l;
        fsplit(v, h, l);
        size_t o = (size_t)(bx + ty + r) * R + by + tx;
        dh[o] = h;
        dl[o] = l;
    }
}

// ------------------------- token shift + xxx split -------------------------
__global__ void shift_kernel(const float* __restrict__ x,
                             const float* __restrict__ maa_x,
                             float* __restrict__ xx,
                             bf16* __restrict__ xxxh,
                             bf16* __restrict__ xxxl)
{
    int i = blockIdx.x * blockDim.x + threadIdx.x;
    if (i >= MT * Cc) return;
    int c = i & (Cc - 1);
    int t = (i >> 10) & (Tc - 1);
    float xv = x[i];
    float xp = (t != 0) ? x[i - Cc] : 0.0f;
    float d  = xp - xv;
    xx[i] = d;
    float v = xv + d * maa_x[c];
    bf16 h, l;
    fsplit(v, h, l);
    xxxh[i] = h;
    xxxl[i] = l;
}

// split-K combine: m = tanh(a+b) -> bf16 pair
__global__ void tanh_combine_kernel(const float* __restrict__ a,
                                    const float* __restrict__ b,
                                    bf16* __restrict__ oh,
                                    bf16* __restrict__ ol, int n)
{
    int i = blockIdx.x * blockDim.x + threadIdx.x;
    if (i < n) {
        float v = tanhf(a[i] + b[i]);
        bf16 h, l;
        fsplit(v, h, l);
        oh[i] = h;
        ol[i] = l;
    }
}

// ==================== chunked WKV6 (3 passes) ==============================
__global__ __launch_bounds__(64)
void wkv6_pass1_kernel(const float* __restrict__ k, const float* __restrict__ v,
                       float* __restrict__ w, float* __restrict__ sc,
                       float* __restrict__ dp)
{
    const int bh = blockIdx.x >> 4;
    const int c  = blockIdx.x & 15;
    const int b  = bh >> 4;
    const int h  = bh & 15;
    const int j  = threadIdx.x;
    const size_t base = (size_t)b * Tc * Cc + h * Kk + j;

    float S[64];
#pragma unroll
    for (int i = 0; i < 64; i++) S[i] = 0.0f;
    float Dj = 1.0f;

    __shared__ float2 q[64];

    const int t0 = c * CLEN;
    for (int t = t0; t < t0 + CLEN; t++) {
        const size_t off = base + (size_t)t * Cc;
        float kj = k[off];
        float vj = v[off];
        float wj = w[off];
        float wd = expf(-expf(wj));
        w[off] = wd;
        Dj *= wd;
        q[j] = make_float2(kj, wd);
        __syncthreads();
#pragma unroll
        for (int i = 0; i < 64; i += 4) {
            float2 q0 = q[i + 0], q1 = q[i + 1], q2 = q[i + 2], q3 = q[i + 3];
            S[i + 0] = fmaf(S[i + 0], q0.y, q0.x * vj);
            S[i + 1] = fmaf(S[i + 1], q1.y, q1.x * vj);
            S[i + 2] = fmaf(S[i + 2], q2.y, q2.x * vj);
            S[i + 3] = fmaf(S[i + 3], q3.y, q3.x * vj);
        }
        __syncthreads();
    }

    float* scp = sc + ((size_t)bh * NCHUNK + c) * (Kk * Kk);
#pragma unroll 8
    for (int i = 0; i < 64; i++) scp[i * 64 + j] = S[i];
    dp[((size_t)bh * NCHUNK + c) * Kk + j] = Dj;
}

__global__ __launch_bounds__(64)
void wkv6_pass2_kernel(float* __restrict__ sc, const float* __restrict__ dp)
{
    const int bh = blockIdx.x;
    const int j  = threadIdx.x;

    float R[64];
#pragma unroll
    for (int i = 0; i < 64; i++) R[i] = 0.0f;

    __shared__ float Ds[64];

    for (int c = 0; c < NCHUNK; c++) {
        Ds[j] = dp[((size_t)bh * NCHUNK + c) * Kk + j];
        __syncthreads();
        float* scp = sc + ((size_t)bh * NCHUNK + c) * (Kk * Kk);
#pragma unroll 4
        for (int i = 0; i < 64; i++) {
            float sl = scp[i * 64 + j];
            scp[i * 64 + j] = R[i];
            R[i] = fmaf(R[i], Ds[i], sl);
        }
        __syncthreads();
    }
}

__global__ __launch_bounds__(64)
void wkv6_pass3_kernel(const float* __restrict__ r, const float* __restrict__ k,
                       const float* __restrict__ v, const float* __restrict__ wd,
                       const float* __restrict__ u, const float* __restrict__ sc,
                       float* __restrict__ y)
{
    const int bh = blockIdx.x >> 4;
    const int c  = blockIdx.x & 15;
    const int b  = bh >> 4;
    const int h  = bh & 15;
    const int j  = threadIdx.x;
    const size_t base = (size_t)b * Tc * Cc + h * Kk + j;
    const float  uj   = u[h * Kk + j];

    float S[64];
    const float* scp = sc + ((size_t)bh * NCHUNK + c) * (Kk * Kk);
#pragma unroll 8
    for (int i = 0; i < 64; i++) S[i] = scp[i * 64 + j];

    __shared__ float4 q[64];

    const int t0 = c * CLEN;
    for (int t = t0; t < t0 + CLEN; t++) {
        const size_t off = base + (size_t)t * Cc;
        float rj = r[off];
        float kj = k[off];
        float dj = wd[off];
        float vj = v[off];
        q[j] = make_float4(rj, kj, dj, uj);
        __syncthreads();

        float y0 = 0.f, y1 = 0.f, y2 = 0.f, y3 = 0.f;
#pragma unroll
        for (int kk = 0; kk < 64; kk += 4) {
            float4 q0 = q[kk + 0];
            float4 q1 = q[kk + 1];
            float4 q2 = q[kk + 2];
            float4 q3 = q[kk + 3];
            float kv0 = q0.y * vj;
            float kv1 = q1.y * vj;
            float kv2 = q2.y * vj;
            float kv3 = q3.y * vj;
            y0 = fmaf(q0.x, fmaf(q0.w, kv0, S[kk + 0]), y0);
            y1 = fmaf(q1.x, fmaf(q1.w, kv1, S[kk + 1]), y1);
            y2 = fmaf(q2.x, fmaf(q2.w, kv2, S[kk + 2]), y2);
            y3 = fmaf(q3.x, fmaf(q3.w, kv3, S[kk + 3]), y3);
            S[kk + 0] = fmaf(S[kk + 0], q0.z, kv0);
            S[kk + 1] = fmaf(S[kk + 1], q1.z, kv1);
            S[kk + 2] = fmaf(S[kk + 2], q2.z, kv2);
            S[kk + 3] = fmaf(S[kk + 3], q3.z, kv3);
        }
        y[off] = (y0 + y1) + (y2 + y3);
        __syncthreads();
    }
}

// ------------------- groupnorm + gate -> z bf16 pair -----------------------
__global__ __launch_bounds__(256)
void gnorm_kernel(const float* __restrict__ y, const float* __restrict__ gate,
                  const float* __restrict__ gamma, const float* __restrict__ beta,
                  bf16* __restrict__ zh, bf16* __restrict__ zl)
{
    const int row = blockIdx.x;
    const int tid = threadIdx.x;
    const int c0  = tid * 4;
    const size_t idx = (size_t)row * Cc + c0;

    float4 yv = *reinterpret_cast<const float4*>(y + idx);
    float s  = yv.x + yv.y + yv.z + yv.w;
    float ss = yv.x * yv.x + yv.y * yv.y + yv.z * yv.z + yv.w * yv.w;
#pragma unroll
    for (int o = 8; o > 0; o >>= 1) {
        s  += __shfl_xor_sync(0xffffffffu, s,  o);
        ss += __shfl_xor_sync(0xffffffffu, ss, o);
    }
    const float mean = s * (1.0f / 64.0f);
    const float var  = ss * (1.0f / 64.0f) - mean * mean;
    const float rstd = rsqrtf(var + EPSC);

    float4 gm = *reinterpret_cast<const float4*>(gamma + c0);
    float4 bt = *reinterpret_cast<const float4*>(beta + c0);
    float4 gt = *reinterpret_cast<const float4*>(gate + idx);
    float o0 = ((yv.x - mean) * rstd * gm.x + bt.x) * gt.x;
    float o1 = ((yv.y - mean) * rstd * gm.y + bt.y) * gt.y;
    float o2 = ((yv.z - mean) * rstd * gm.z + bt.z) * gt.z;
    float o3 = ((yv.w - mean) * rstd * gm.w + bt.w) * gt.w;

    bf16 h0, l0, h1, l1, h2, l2, h3, l3;
    fsplit(o0, h0, l0); fsplit(o1, h1, l1);
    fsplit(o2, h2, l2); fsplit(o3, h3, l3);
    *reinterpret_cast<__nv_bfloat162*>(zh + idx)     = __nv_bfloat162(h0, h1);
    *reinterpret_cast<__nv_bfloat162*>(zh + idx + 2) = __nv_bfloat162(h2, h3);
    *reinterpret_cast<__nv_bfloat162*>(zl + idx)     = __nv_bfloat162(l0, l1);
    *reinterpret_cast<__nv_bfloat162*>(zl + idx + 2) = __nv_bfloat162(l2, l3);
}

// ---------------------------------------------------------------------------
extern "C" void kernel_launch(void* const* d_in, const int* in_sizes, int n_in,
                              void* d_out, int out_size)
{
    const float* x      = (const float*)d_in[0];
    const float* maa_x  = (const float*)d_in[1];
    const float* maa_w  = (const float*)d_in[2];
    const float* maa_k  = (const float*)d_in[3];
    const float* maa_v  = (const float*)d_in[4];
    const float* maa_r  = (const float*)d_in[5];
    const float* maa_g  = (const float*)d_in[6];
    const float* maa_w1 = (const float*)d_in[7];
    const float* maa_w2 = (const float*)d_in[8];
    const float* tdecay = (const float*)d_in[9];
    const float* dw1    = (const float*)d_in[10];
    const float* dw2    = (const float*)d_in[11];
    const float* u      = (const float*)d_in[12];
    const float* W_r    = (const float*)d_in[13];
    const float* W_k    = (const float*)d_in[14];
    const float* W_v    = (const float*)d_in[15];
    const float* W_g    = (const float*)d_in[16];
    const float* W_o    = (const float*)d_in[17];
    const float* gamma  = (const float*)d_in[18];
    const float* beta   = (const float*)d_in[19];
    float* out = (float*)d_out;

    float *xx, *ms0, *ms1, *rr, *kk, *vv, *gg, *ww, *y, *sc, *dpp;
    bf16 *wt5h, *wt5l, *w1th, *w1tl, *w2th, *w2tl, *dw1th, *dw1tl, *dw2th, *dw2tl;
    bf16 *xxxh, *xxxl, *mh, *ml, *xwh, *xwl, *xkh, *xkl, *xvh, *xvl;
    bf16 *xrh, *xrl, *xgh, *xgl, *t64h, *t64l, *zh, *zl;
    cudaGetSymbolAddress((void**)&xx,    g_xx);
    cudaGetSymbolAddress((void**)&ms0,   g_ms0);
    cudaGetSymbolAddress((void**)&ms1,   g_ms1);
    cudaGetSymbolAddress((void**)&rr,    g_r);
    cudaGetSymbolAddress((void**)&kk,    g_k);
    cudaGetSymbolAddress((void**)&vv,    g_v);
    cudaGetSymbolAddress((void**)&gg,    g_g);
    cudaGetSymbolAddress((void**)&ww,    g_w);
    cudaGetSymbolAddress((void**)&y,     g_y);
    cudaGetSymbolAddress((void**)&sc,    g_sc);
    cudaGetSymbolAddress((void**)&dpp,   g_dp);
    cudaGetSymbolAddress((void**)&wt5h,  g_wt5h);
    cudaGetSymbolAddress((void**)&wt5l,  g_wt5l);
    cudaGetSymbolAddress((void**)&w1th,  g_w1th);
    cudaGetSymbolAddress((void**)&w1tl,  g_w1tl);
    cudaGetSymbolAddress((void**)&w2th,  g_w2th);
    cudaGetSymbolAddress((void**)&w2tl,  g_w2tl);
    cudaGetSymbolAddress((void**)&dw1th, g_dw1th);
    cudaGetSymbolAddress((void**)&dw1tl, g_dw1tl);
    cudaGetSymbolAddress((void**)&dw2th, g_dw2th);
    cudaGetSymbolAddress((void**)&dw2tl, g_dw2tl);
    cudaGetSymbolAddress((void**)&xxxh,  g_xxxh);
    cudaGetSymbolAddress((void**)&xxxl,  g_xxxl);
    cudaGetSymbolAddress((void**)&mh,    g_mh);
    cudaGetSymbolAddress((void**)&ml,    g_ml);
    cudaGetSymbolAddress((void**)&xwh,   g_xwh);
    cudaGetSymbolAddress((void**)&xwl,   g_xwl);
    cudaGetSymbolAddress((void**)&xkh,   g_xkh);
    cudaGetSymbolAddress((void**)&xkl,   g_xkl);
    cudaGetSymbolAddress((void**)&xvh,   g_xvh);
    cudaGetSymbolAddress((void**)&xvl,   g_xvl);
    cudaGetSymbolAddress((void**)&xrh,   g_xrh);
    cudaGetSymbolAddress((void**)&xrl,   g_xrl);
    cudaGetSymbolAddress((void**)&xgh,   g_xgh);
    cudaGetSymbolAddress((void**)&xgl,   g_xgl);
    cudaGetSymbolAddress((void**)&t64h,  g_t64h);
    cudaGetSymbolAddress((void**)&t64l,  g_t64l);
    cudaGetSymbolAddress((void**)&zh,    g_zh);
    cudaGetSymbolAddress((void**)&zl,    g_zl);

    cudaFuncSetAttribute(gemm_bf16x3_kernel,
                         cudaFuncAttributeMaxDynamicSharedMemorySize, GSMEM_BYTES);

    const size_t WSZ = (size_t)Cc * Cc;
    dim3 tb(32, 8);

    // 0a) big weight transposes + split
    {
        TBatch j = {};
        const float* s5[5] = {W_r, W_k, W_v, W_g, W_o};
        for (int f = 0; f < 5; f++) {
            j.src[f] = s5[f];
            j.dsth[f] = wt5h + (size_t)f * WSZ;
            j.dstl[f] = wt5l + (size_t)f * WSZ;
            j.R[f] = 1024; j.C[f] = 1024;
        }
        for (int f = 5; f < 8; f++) {
            j.src[f] = W_r; j.dsth[f] = wt5h; j.dstl[f] = wt5l;
            j.R[f] = 0; j.C[f] = 0;
        }
        transpose_split_kernel<<<dim3(32, 32, 5), tb>>>(j);
    }
    // 0b) small transposes + split
    {
        TBatch j = {};
        j.src[0] = maa_w1; j.dsth[0] = w1th; j.dstl[0] = w1tl;
        j.R[0] = 1024; j.C[0] = 160;
        for (int f = 0; f < 5; f++) {
            j.src[1 + f]  = maa_w2 + (size_t)f * 32 * 1024;
            j.dsth[1 + f] = w2th + (size_t)f * 1024 * 32;
            j.dstl[1 + f] = w2tl + (size_t)f * 1024 * 32;
            j.R[1 + f] = 32; j.C[1 + f] = 1024;
        }
        j.src[6] = dw1; j.dsth[6] = dw1th; j.dstl[6] = dw1tl;
        j.R[6] = 1024; j.C[6] = 64;
        j.src[7] = dw2; j.dsth[7] = dw2th; j.dstl[7] = dw2tl;
        j.R[7] = 64; j.C[7] = 1024;
        transpose_split_kernel<<<dim3(32, 32, 8), tb>>>(j);
    }

    // 1) token shift (+ xxx split)
    shift_kernel<<<(MT * Cc + 255) / 256, 256>>>(x, maa_x, xx, xxxh, xxxl);

    // 2) m = tanh(xxx @ W1), split-K=2, combine writes bf16 pair
    {
        GemmBatch a = {};
        a.Ah[0] = xxxh;       a.Al[0] = xxxl;
        a.Bh[0] = w1th;       a.Bl[0] = w1tl;
        a.Ah[1] = xxxh + 512; a.Al[1] = xxxl + 512;
        a.Bh[1] = w1th + 512; a.Bl[1] = w1tl + 512;
        a.C[0] = ms0; a.C[1] = ms1;
        a.N[0] = a.N[1] = 160; a.ldc[0] = a.ldc[1] = 160;
        a.epi[0] = a.epi[1] = EPI_NONE; a.pair[0] = a.pair[1] = 0;
        a.K = 512; a.lda = 1024; a.ldb = 1024;
        gemm_bf16x3_kernel<<<dim3(2, 32, 2), 256, GSMEM_BYTES>>>(a);
        tanh_combine_kernel<<<(MT * 160 + 255) / 256, 256>>>(ms0, ms1, mh, ml, MT * 160);
    }

    // 3) five mixing GEMMs -> bf16 pair outputs
    {
        GemmBatch a = {};
        const float* bias5[5] = {maa_w, maa_k, maa_v, maa_r, maa_g};
        bf16* oh[5] = {xwh, xkh, xvh, xrh, xgh};
        bf16* ol[5] = {xwl, xkl, xvl, xrl, xgl};
        for (int f = 0; f < 5; f++) {
            a.Ah[f] = mh + f * 32; a.Al[f] = ml + f * 32;
            a.Bh[f] = w2th + (size_t)f * 1024 * 32;
            a.Bl[f] = w2tl + (size_t)f * 1024 * 32;
            a.Ch[f] = oh[f]; a.Cl[f] = ol[f];
            a.bias[f] = bias5[f];
            a.N[f] = 1024; a.ldc[f] = 1024; a.epi[f] = EPI_MIX; a.pair[f] = 1;
        }
        a.ex = x; a.exx = xx;
        a.K = 32; a.lda = 160; a.ldb = 32;
        gemm_bf16x3_kernel<<<dim3(8, 32, 5), 256, GSMEM_BYTES>>>(a);
    }

    // 4) projections r/k/v/g (f32 out) + decay LoRA-1 (bf16-pair out)
    {
        GemmBatch a = {};
        const bf16* Ahs[5] = {xrh, xkh, xvh, xgh, xwh};
        const bf16* Als[5] = {xrl, xkl, xvl, xgl, xwl};
        const bf16* Bhs[5] = {wt5h + 0 * WSZ, wt5h + 1 * WSZ, wt5h + 2 * WSZ,
                              wt5h + 3 * WSZ, dw1th};
        const bf16* Bls[5] = {wt5l + 0 * WSZ, wt5l + 1 * WSZ, wt5l + 2 * WSZ,
                              wt5l + 3 * WSZ, dw1tl};
        float* Cs[5] = {rr, kk, vv, gg, nullptr};
        int Ns[5]   = {1024, 1024, 1024, 1024, 64};
        int ldcs[5] = {1024, 1024, 1024, 1024, 64};
        int epis[5] = {EPI_NONE, EPI_NONE, EPI_NONE, EPI_SILU, EPI_TANH};
        int prs[5]  = {0, 0, 0, 0, 1};
        for (int f = 0; f < 5; f++) {
            a.Ah[f] = Ahs[f]; a.Al[f] = Als[f];
            a.Bh[f] = Bhs[f]; a.Bl[f] = Bls[f];
            a.C[f] = Cs[f];
            a.N[f] = Ns[f]; a.ldc[f] = ldcs[f]; a.epi[f] = epis[f]; a.pair[f] = prs[f];
        }
        a.Ch[4] = t64h; a.Cl[4] = t64l;
        a.K = 1024; a.lda = 1024; a.ldb = 1024;
        gemm_bf16x3_kernel<<<dim3(8, 32, 5), 256, GSMEM_BYTES>>>(a);
    }

    // 5) decay LoRA-2: w = time_decay + t64 @ dw2  (f32 out)
    {
        GemmBatch a = {};
        a.Ah[0] = t64h; a.Al[0] = t64l;
        a.Bh[0] = dw2th; a.Bl[0] = dw2tl;
        a.C[0] = ww; a.bias[0] = tdecay;
        a.N[0] = 1024; a.ldc[0] = 1024; a.epi[0] = EPI_BIAS; a.pair[0] = 0;
        a.K = 64; a.lda = 64; a.ldb = 64;
        gemm_bf16x3_kernel<<<dim3(8, 32, 1), 256, GSMEM_BYTES>>>(a);
    }

    // 6) chunked WKV6 scan
    wkv6_pass1_kernel<<<64 * NCHUNK, 64>>>(kk, vv, ww, sc, dpp);
    wkv6_pass2_kernel<<<64, 64>>>(sc, dpp);
    wkv6_pass3_kernel<<<64 * NCHUNK, 64>>>(rr, kk, vv, ww, u, sc, y);

    // 7) groupnorm + gate -> z bf16 pair
    gnorm_kernel<<<MT, 256>>>(y, gg, gamma, beta, zh, zl);

    // 8) output projection
    {
        GemmBatch a = {};
        a.Ah[0] = zh; a.Al[0] = zl;
        a.Bh[0] = wt5h + 4 * WSZ; a.Bl[0] = wt5l + 4 * WSZ;
        a.C[0] = out;
        a.N[0] = 1024; a.ldc[0] = 1024; a.epi[0] = EPI_NONE; a.pair[0] = 0;
        a.K = 1024; a.lda = 1024; a.ldb = 1024;
        gemm_bf16x3_kernel<<<dim3(8, 32, 1), 256, GSMEM_BYTES>>>(a);
    }
}

// round 16
// speedup vs baseline: 3.1998x; 1.0274x over previous
#include <cuda_runtime.h>
#include <cuda_bf16.h>
#include <math.h>
#include <stdint.h>

// ---------------------------------------------------------------------------
// RWKV v6 TimeMix  (B=4, T=1024, C=1024, H=16, K=64)
// Round 16 (resubmit of R15; container flake): bf16x3 GEMM mainloop with
// ldmatrix fragment loads (24 LDSM vs 96 LDS per BK-iter).
// ---------------------------------------------------------------------------

#define Bc 4
#define Tc 1024
#define Cc 1024
#define Hh 16
#define Kk 64
#define MT (Bc * Tc)
#define EPSC (1e-5f * 64.0f)
#define NCHUNK 16
#define CLEN   64

typedef __nv_bfloat16 bf16;

// ------------------------- scratch (static device mem) ---------------------
__device__ float g_xx  [MT * Cc];
__device__ float g_ms0 [MT * 160];
__device__ float g_ms1 [MT * 160];
__device__ float g_r   [MT * Cc];
__device__ float g_k   [MT * Cc];
__device__ float g_v   [MT * Cc];
__device__ float g_g   [MT * Cc];
__device__ float g_w   [MT * Cc];
__device__ float g_y   [MT * Cc];
__device__ float g_sc  [64 * NCHUNK * Kk * Kk];
__device__ float g_dp  [64 * NCHUNK * Kk];
// bf16 hi/lo planes (256B-aligned for cp.async 16B global loads)
__device__ __align__(256) bf16 g_wt5h [5 * Cc * Cc];
__device__ __align__(256) bf16 g_wt5l [5 * Cc * Cc];
__device__ __align__(256) bf16 g_w1th [160 * Cc];
__device__ __align__(256) bf16 g_w1tl [160 * Cc];
__device__ __align__(256) bf16 g_w2th [5 * Cc * 32];
__device__ __align__(256) bf16 g_w2tl [5 * Cc * 32];
__device__ __align__(256) bf16 g_dw1th[64 * Cc];
__device__ __align__(256) bf16 g_dw1tl[64 * Cc];
__device__ __align__(256) bf16 g_dw2th[Cc * 64];
__device__ __align__(256) bf16 g_dw2tl[Cc * 64];
__device__ __align__(256) bf16 g_xxxh [MT * Cc];
__device__ __align__(256) bf16 g_xxxl [MT * Cc];
__device__ __align__(256) bf16 g_mh   [MT * 160];
__device__ __align__(256) bf16 g_ml   [MT * 160];
__device__ __align__(256) bf16 g_xwh  [MT * Cc];
__device__ __align__(256) bf16 g_xwl  [MT * Cc];
__device__ __align__(256) bf16 g_xkh  [MT * Cc];
__device__ __align__(256) bf16 g_xkl  [MT * Cc];
__device__ __align__(256) bf16 g_xvh  [MT * Cc];
__device__ __align__(256) bf16 g_xvl  [MT * Cc];
__device__ __align__(256) bf16 g_xrh  [MT * Cc];
__device__ __align__(256) bf16 g_xrl  [MT * Cc];
__device__ __align__(256) bf16 g_xgh  [MT * Cc];
__device__ __align__(256) bf16 g_xgl  [MT * Cc];
__device__ __align__(256) bf16 g_t64h [MT * 64];
__device__ __align__(256) bf16 g_t64l [MT * 64];
__device__ __align__(256) bf16 g_zh   [MT * Cc];
__device__ __align__(256) bf16 g_zl   [MT * Cc];

__device__ __forceinline__ void fsplit(float v, bf16& h, bf16& l) {
    h = __float2bfloat16(v);
    l = __float2bfloat16(v - __bfloat162float(h));
}

// ======================= bf16x3 mma.sync GEMM ==============================
enum { EPI_NONE = 0, EPI_TANH = 1, EPI_SILU = 2, EPI_BIAS = 3, EPI_MIX = 4 };

struct GemmBatch {
    const bf16* Ah[5]; const bf16* Al[5];
    const bf16* Bh[5]; const bf16* Bl[5];
    float*      C[5];
    bf16*       Ch[5]; bf16* Cl[5];
    const float* bias[5];
    int N[5], ldc[5], epi[5], pair[5];
    const float* ex; const float* exx;
    int K, lda, ldb;
};

// stage: 4 planes (Ah,Al,Bh,Bl), each 128 rows x 80B (32 bf16 = 64B + 16B pad)
#define ROWB       80u
#define PLANE_B    10240u               // 128*80
#define GSTAGE_B   40960u
#define GSMEM_BYTES (2u * GSTAGE_B)     // 81920 -> 2 CTAs/SM

__device__ __forceinline__ void cp16(uint32_t saddr, const void* gptr, int sz) {
    asm volatile("cp.async.cg.shared.global [%0], [%1], 16, %2;"
                 :: "r"(saddr), "l"(gptr), "r"(sz));
}
__device__ __forceinline__ void cp_commit() {
    asm volatile("cp.async.commit_group;" ::: "memory");
}
__device__ __forceinline__ void cp_wait1() {
    asm volatile("cp.async.wait_group 1;" ::: "memory");
}
__device__ __forceinline__ uint32_t smem_u32(const void* p) {
    uint32_t a;
    asm("{ .reg .u64 t; cvta.to.shared.u64 t, %1; cvt.u32.u64 %0, t; }"
        : "=r"(a) : "l"(p));
    return a;
}
__device__ __forceinline__ void mma_bf16(float c[4],
    uint32_t a0, uint32_t a1, uint32_t a2, uint32_t a3, uint32_t b0, uint32_t b1)
{
    asm volatile(
        "mma.sync.aligned.m16n8k16.row.col.f32.bf16.bf16.f32 "
        "{%0,%1,%2,%3}, {%4,%5,%6,%7}, {%8,%9}, {%0,%1,%2,%3};"
        : "+f"(c[0]), "+f"(c[1]), "+f"(c[2]), "+f"(c[3])
        : "r"(a0), "r"(a1), "r"(a2), "r"(a3), "r"(b0), "r"(b1));
}
#define LDSM4(r0, r1, r2, r3, addr) \
    asm volatile("ldmatrix.sync.aligned.m8n8.x4.shared.b16 {%0,%1,%2,%3}, [%4];" \
        : "=r"(r0), "=r"(r1), "=r"(r2), "=r"(r3) : "r"(addr))

__global__ void __launch_bounds__(256, 2)
gemm_bf16x3_kernel(const GemmBatch args)
{
    extern __shared__ char smem[];
    const int z  = blockIdx.z;
    const int Nz = args.N[z];
    const int n0 = blockIdx.x * 128;
    if (n0 >= Nz) return;
    const int m0 = blockIdx.y * 128;

    const int tid = threadIdx.x;
    const int wid = tid >> 5;
    const int lid = tid & 31;
    const int wm  = wid >> 2;
    const int wn  = wid & 3;
    const int gid = lid >> 2;
    const int tig = lid & 3;

    const int lda = args.lda, ldb = args.ldb, K = args.K;
    const int NIT = K >> 5;

    const int arow = tid >> 1;
    const int side = tid & 1;
    const uint32_t sbase = smem_u32(smem);
    const int brow_ok = (n0 + arow) < Nz;
    const int bsz = brow_ok ? 16 : 0;
    const int brow = brow_ok ? (n0 + arow) : 0;

    const bf16* gAh = args.Ah[z] + (size_t)(m0 + arow) * lda + side * 16;
    const bf16* gAl = args.Al[z] + (size_t)(m0 + arow) * lda + side * 16;
    const bf16* gBh = args.Bh[z] + (size_t)brow * ldb + side * 16;
    const bf16* gBl = args.Bl[z] + (size_t)brow * ldb + side * 16;

    auto load_stage = [&](int st, int kt) {
        const uint32_t rb = sbase + (uint32_t)st * GSTAGE_B
                          + (uint32_t)arow * ROWB + (uint32_t)side * 32u;
        const int ke = kt * 32;
        cp16(rb,                     gAh + ke,     16);
        cp16(rb + 16u,               gAh + ke + 8, 16);
        cp16(rb + PLANE_B,           gAl + ke,     16);
        cp16(rb + PLANE_B + 16u,     gAl + ke + 8, 16);
        cp16(rb + 2 * PLANE_B,       gBh + ke,     bsz);
        cp16(rb + 2 * PLANE_B + 16u, gBh + ke + 8, bsz);
        cp16(rb + 3 * PLANE_B,       gBl + ke,     bsz);
        cp16(rb + 3 * PLANE_B + 16u, gBl + ke + 8, bsz);
    };

    float c[4][4][4];
#pragma unroll
    for (int mt = 0; mt < 4; mt++)
#pragma unroll
        for (int nt = 0; nt < 4; nt++)
#pragma unroll
            for (int i = 0; i < 4; i++) c[mt][nt][i] = 0.0f;

    // ldmatrix per-thread offsets (within stage)
    uint32_t aoff[4];
#pragma unroll
    for (int mt = 0; mt < 4; mt++)
        aoff[mt] = (uint32_t)(wm * 64 + mt * 16 + (lid & 15)) * ROWB
                 + (uint32_t)(lid >> 4) * 16u;
    uint32_t boff[4];
#pragma unroll
    for (int nt = 0; nt < 4; nt++)
        boff[nt] = 2u * PLANE_B
                 + (uint32_t)(wn * 32 + nt * 8 + (lid & 7)) * ROWB
                 + (uint32_t)(lid >> 3) * 16u;

    // 2-stage pipeline: prologue loads stage 0
    load_stage(0, 0);
    cp_commit();

    for (int kt = 0; kt < NIT; kt++) {
        if (kt + 1 < NIT) load_stage((kt + 1) & 1, kt + 1);
        cp_commit();
        cp_wait1();
        __syncthreads();

        const uint32_t stb = sbase + (uint32_t)(kt & 1) * GSTAGE_B;

        // B fragments for both k-steps: [nt][0..1]=ks0 b0/b1, [2..3]=ks1
        uint32_t bh[4][4], bl[4][4];
#pragma unroll
        for (int nt = 0; nt < 4; nt++) {
            LDSM4(bh[nt][0], bh[nt][1], bh[nt][2], bh[nt][3], stb + boff[nt]);
            LDSM4(bl[nt][0], bl[nt][1], bl[nt][2], bl[nt][3],
                  stb + boff[nt] + PLANE_B);
        }

#pragma unroll
        for (int ks = 0; ks < 2; ks++) {
#pragma unroll
            for (int mt = 0; mt < 4; mt++) {
                const uint32_t aa = stb + aoff[mt] + (uint32_t)ks * 32u;
                uint32_t ah0, ah1, ah2, ah3, al0, al1, al2, al3;
                LDSM4(ah0, ah1, ah2, ah3, aa);
                LDSM4(al0, al1, al2, al3, aa + PLANE_B);
#pragma unroll
                for (int nt = 0; nt < 4; nt++) {
                    mma_bf16(c[mt][nt], ah0, ah1, ah2, ah3,
                             bh[nt][2 * ks], bh[nt][2 * ks + 1]);
                    mma_bf16(c[mt][nt], ah0, ah1, ah2, ah3,
                             bl[nt][2 * ks], bl[nt][2 * ks + 1]);
                    mma_bf16(c[mt][nt], al0, al1, al2, al3,
                             bh[nt][2 * ks], bh[nt][2 * ks + 1]);
                }
            }
        }
        __syncthreads();
    }

    // -------- epilogue --------
    const int ep   = args.epi[z];
    const int pair = args.pair[z];
    const float* bias = args.bias[z];
    const int ldc = args.ldc[z];
    float* Cg = args.C[z];
    bf16*  Chg = args.Ch[z];
    bf16*  Clg = args.Cl[z];
    const float* ex  = args.ex;
    const float* exx = args.exx;

    auto apply2 = [&](float& v0, float& v1, int row, int col) {
        if (ep == EPI_TANH) { v0 = tanhf(v0); v1 = tanhf(v1); }
        else if (ep == EPI_SILU) {
            v0 = v0 / (1.0f + expf(-v0));
            v1 = v1 / (1.0f + expf(-v1));
        } else if (ep == EPI_BIAS) { v0 += bias[col]; v1 += bias[col + 1]; }
        else if (ep == EPI_MIX) {
            size_t idx = (size_t)row * 1024 + col;
            float2 e  = *reinterpret_cast<const float2*>(ex  + idx);
            float2 dx = *reinterpret_cast<const float2*>(exx + idx);
            v0 = e.x + dx.x * (bias[col]     + v0);
            v1 = e.y + dx.y * (bias[col + 1] + v1);
        }
    };
    auto store2 = [&](float v0, float v1, int row, int col) {
        if (pair) {
            bf16 h0, l0, h1, l1;
            fsplit(v0, h0, l0);
            fsplit(v1, h1, l1);
            *reinterpret_cast<__nv_bfloat162*>(Chg + (size_t)row * ldc + col)
                = __nv_bfloat162(h0, h1);
            *reinterpret_cast<__nv_bfloat162*>(Clg + (size_t)row * ldc + col)
                = __nv_bfloat162(l0, l1);
        } else {
            *reinterpret_cast<float2*>(Cg + (size_t)row * ldc + col)
                = make_float2(v0, v1);
        }
    };

#pragma unroll
    for (int mt = 0; mt < 4; mt++) {
        const int r0 = m0 + wm * 64 + mt * 16 + gid;
#pragma unroll
        for (int nt = 0; nt < 4; nt++) {
            const int col = n0 + wn * 32 + nt * 8 + tig * 2;
            if (col < Nz) {
                float v0 = c[mt][nt][0], v1 = c[mt][nt][1];
                apply2(v0, v1, r0, col);
                store2(v0, v1, r0, col);
                float v2 = c[mt][nt][2], v3 = c[mt][nt][3];
                apply2(v2, v3, r0 + 8, col);
                store2(v2, v3, r0 + 8, col);
            }
        }
    }
}

// ------------------- batched transpose + bf16 split ------------------------
struct TBatch {
    const float* src[8];
    bf16* dsth[8]; bf16* dstl[8];
    int R[8], C[8];
};

__global__ void transpose_split_kernel(const TBatch jobs)
{
    __shared__ float tile[32][33];
    const int z = blockIdx.z;
    const int bx = blockIdx.x * 32, by = blockIdx.y * 32;
    const int R = jobs.R[z], C = jobs.C[z];
    if (bx >= C || by >= R) return;
    const float* src = jobs.src[z];
    bf16* dh = jobs.dsth[z];
    bf16* dl = jobs.dstl[z];
    const int tx = threadIdx.x, ty = threadIdx.y;
#pragma unroll
    for (int r = 0; r < 32; r += 8)
        tile[ty + r][tx] = src[(size_t)(by + ty + r) * C + bx + tx];
    __syncthreads();
#pragma unroll
    for (int r = 0; r < 32; r += 8) {
        float v = tile[tx][ty + r];
        bf16 h, l;
        fsplit(v, h, l);
        size_t o = (size_t)(bx + ty + r) * R + by + tx;
        dh[o] = h;
        dl[o] = l;
    }
}

// ------------------------- token shift + xxx split -------------------------
__global__ void shift_kernel(const float* __restrict__ x,
                             const float* __restrict__ maa_x,
                             float* __restrict__ xx,
                             bf16* __restrict__ xxxh,
                             bf16* __restrict__ xxxl)
{
    int i = blockIdx.x * blockDim.x + threadIdx.x;
    if (i >= MT * Cc) return;
    int c = i & (Cc - 1);
    int t = (i >> 10) & (Tc - 1);
    float xv = x[i];
    float xp = (t != 0) ? x[i - Cc] : 0.0f;
    float d  = xp - xv;
    xx[i] = d;
    float v = xv + d * maa_x[c];
    bf16 h, l;
    fsplit(v, h, l);
    xxxh[i] = h;
    xxxl[i] = l;
}

// split-K combine: m = tanh(a+b) -> bf16 pair
__global__ void tanh_combine_kernel(const float* __restrict__ a,
                                    const float* __restrict__ b,
                                    bf16* __restrict__ oh,
                                    bf16* __restrict__ ol, int n)
{
    int i = blockIdx.x * blockDim.x + threadIdx.x;
    if (i < n) {
        float v = tanhf(a[i] + b[i]);
        bf16 h, l;
        fsplit(v, h, l);
        oh[i] = h;
        ol[i] = l;
    }
}

// ==================== chunked WKV6 (3 passes) ==============================
__global__ __launch_bounds__(64)
void wkv6_pass1_kernel(const float* __restrict__ k, const float* __restrict__ v,
                       float* __restrict__ w, float* __restrict__ sc,
                       float* __restrict__ dp)
{
    const int bh = blockIdx.x >> 4;
    const int c  = blockIdx.x & 15;
    const int b  = bh >> 4;
    const int h  = bh & 15;
    const int j  = threadIdx.x;
    const size_t base = (size_t)b * Tc * Cc + h * Kk + j;

    float S[64];
#pragma unroll
    for (int i = 0; i < 64; i++) S[i] = 0.0f;
    float Dj = 1.0f;

    __shared__ float2 q[64];

    const int t0 = c * CLEN;
    for (int t = t0; t < t0 + CLEN; t++) {
        const size_t off = base + (size_t)t * Cc;
        float kj = k[off];
        float vj = v[off];
        float wj = w[off];
        float wd = expf(-expf(wj));
        w[off] = wd;
        Dj *= wd;
        q[j] = make_float2(kj, wd);
        __syncthreads();
#pragma unroll
        for (int i = 0; i < 64; i += 4) {
            float2 q0 = q[i + 0], q1 = q[i + 1], q2 = q[i + 2], q3 = q[i + 3];
            S[i + 0] = fmaf(S[i + 0], q0.y, q0.x * vj);
            S[i + 1] = fmaf(S[i + 1], q1.y, q1.x * vj);
            S[i + 2] = fmaf(S[i + 2], q2.y, q2.x * vj);
            S[i + 3] = fmaf(S[i + 3], q3.y, q3.x * vj);
        }
        __syncthreads();
    }

    float* scp = sc + ((size_t)bh * NCHUNK + c) * (Kk * Kk);
#pragma unroll 8
    for (int i = 0; i < 64; i++) scp[i * 64 + j] = S[i];
    dp[((size_t)bh * NCHUNK + c) * Kk + j] = Dj;
}

__global__ __launch_bounds__(64)
void wkv6_pass2_kernel(float* __restrict__ sc, const float* __restrict__ dp)
{
    const int bh = blockIdx.x;
    const int j  = threadIdx.x;

    float R[64];
#pragma unroll
    for (int i = 0; i < 64; i++) R[i] = 0.0f;

    __shared__ float Ds[64];

    for (int c = 0; c < NCHUNK; c++) {
        Ds[j] = dp[((size_t)bh * NCHUNK + c) * Kk + j];
        __syncthreads();
        float* scp = sc + ((size_t)bh * NCHUNK + c) * (Kk * Kk);
#pragma unroll 4
        for (int i = 0; i < 64; i++) {
            float sl = scp[i * 64 + j];
            scp[i * 64 + j] = R[i];
            R[i] = fmaf(R[i], Ds[i], sl);
        }
        __syncthreads();
    }
}

__global__ __launch_bounds__(64)
void wkv6_pass3_kernel(const float* __restrict__ r, const float* __restrict__ k,
                       const float* __restrict__ v, const float* __restrict__ wd,
                       const float* __restrict__ u, const float* __restrict__ sc,
                       float* __restrict__ y)
{
    const int bh = blockIdx.x >> 4;
    const int c  = blockIdx.x & 15;
    const int b  = bh >> 4;
    const int h  = bh & 15;
    const int j  = threadIdx.x;
    const size_t base = (size_t)b * Tc * Cc + h * Kk + j;
    const float  uj   = u[h * Kk + j];

    float S[64];
    const float* scp = sc + ((size_t)bh * NCHUNK + c) * (Kk * Kk);
#pragma unroll 8
    for (int i = 0; i < 64; i++) S[i] = scp[i * 64 + j];

    __shared__ float4 q[64];

    const int t0 = c * CLEN;
    for (int t = t0; t < t0 + CLEN; t++) {
        const size_t off = base + (size_t)t * Cc;
        float rj = r[off];
        float kj = k[off];
        float dj = wd[off];
        float vj = v[off];
        q[j] = make_float4(rj, kj, dj, uj);
        __syncthreads();

        float y0 = 0.f, y1 = 0.f, y2 = 0.f, y3 = 0.f;
#pragma unroll
        for (int kk = 0; kk < 64; kk += 4) {
            float4 q0 = q[kk + 0];
            float4 q1 = q[kk + 1];
            float4 q2 = q[kk + 2];
            float4 q3 = q[kk + 3];
            float kv0 = q0.y * vj;
            float kv1 = q1.y * vj;
            float kv2 = q2.y * vj;
            float kv3 = q3.y * vj;
            y0 = fmaf(q0.x, fmaf(q0.w, kv0, S[kk + 0]), y0);
            y1 = fmaf(q1.x, fmaf(q1.w, kv1, S[kk + 1]), y1);
            y2 = fmaf(q2.x, fmaf(q2.w, kv2, S[kk + 2]), y2);
            y3 = fmaf(q3.x, fmaf(q3.w, kv3, S[kk + 3]), y3);
            S[kk + 0] = fmaf(S[kk + 0], q0.z, kv0);
            S[kk + 1] = fmaf(S[kk + 1], q1.z, kv1);
            S[kk + 2] = fmaf(S[kk + 2], q2.z, kv2);
            S[kk + 3] = fmaf(S[kk + 3], q3.z, kv3);
        }
        y[off] = (y0 + y1) + (y2 + y3);
        __syncthreads();
    }
}

// ------------------- groupnorm + gate -> z bf16 pair -----------------------
__global__ __launch_bounds__(256)
void gnorm_kernel(const float* __restrict__ y, const float* __restrict__ gate,
                  const float* __restrict__ gamma, const float* __restrict__ beta,
                  bf16* __restrict__ zh, bf16* __restrict__ zl)
{
    const int row = blockIdx.x;
    const int tid = threadIdx.x;
    const int c0  = tid * 4;
    const size_t idx = (size_t)row * Cc + c0;

    float4 yv = *reinterpret_cast<const float4*>(y + idx);
    float s  = yv.x + yv.y + yv.z + yv.w;
    float ss = yv.x * yv.x + yv.y * yv.y + yv.z * yv.z + yv.w * yv.w;
#pragma unroll
    for (int o = 8; o > 0; o >>= 1) {
        s  += __shfl_xor_sync(0xffffffffu, s,  o);
        ss += __shfl_xor_sync(0xffffffffu, ss, o);
    }
    const float mean = s * (1.0f / 64.0f);
    const float var  = ss * (1.0f / 64.0f) - mean * mean;
    const float rstd = rsqrtf(var + EPSC);

    float4 gm = *reinterpret_cast<const float4*>(gamma + c0);
    float4 bt = *reinterpret_cast<const float4*>(beta + c0);
    float4 gt = *reinterpret_cast<const float4*>(gate + idx);
    float o0 = ((yv.x - mean) * rstd * gm.x + bt.x) * gt.x;
    float o1 = ((yv.y - mean) * rstd * gm.y + bt.y) * gt.y;
    float o2 = ((yv.z - mean) * rstd * gm.z + bt.z) * gt.z;
    float o3 = ((yv.w - mean) * rstd * gm.w + bt.w) * gt.w;

    bf16 h0, l0, h1, l1, h2, l2, h3, l3;
    fsplit(o0, h0, l0); fsplit(o1, h1, l1);
    fsplit(o2, h2, l2); fsplit(o3, h3, l3);
    *reinterpret_cast<__nv_bfloat162*>(zh + idx)     = __nv_bfloat162(h0, h1);
    *reinterpret_cast<__nv_bfloat162*>(zh + idx + 2) = __nv_bfloat162(h2, h3);
    *reinterpret_cast<__nv_bfloat162*>(zl + idx)     = __nv_bfloat162(l0, l1);
    *reinterpret_cast<__nv_bfloat162*>(zl + idx + 2) = __nv_bfloat162(l2, l3);
}

// ---------------------------------------------------------------------------
extern "C" void kernel_launch(void* const* d_in, const int* in_sizes, int n_in,
                              void* d_out, int out_size)
{
    const float* x      = (const float*)d_in[0];
    const float* maa_x  = (const float*)d_in[1];
    const float* maa_w  = (const float*)d_in[2];
    const float* maa_k  = (const float*)d_in[3];
    const float* maa_v  = (const float*)d_in[4];
    const float* maa_r  = (const float*)d_in[5];
    const float* maa_g  = (const float*)d_in[6];
    const float* maa_w1 = (const float*)d_in[7];
    const float* maa_w2 = (const float*)d_in[8];
    const float* tdecay = (const float*)d_in[9];
    const float* dw1    = (const float*)d_in[10];
    const float* dw2    = (const float*)d_in[11];
    const float* u      = (const float*)d_in[12];
    const float* W_r    = (const float*)d_in[13];
    const float* W_k    = (const float*)d_in[14];
    const float* W_v    = (const float*)d_in[15];
    const float* W_g    = (const float*)d_in[16];
    const float* W_o    = (const float*)d_in[17];
    const float* gamma  = (const float*)d_in[18];
    const float* beta   = (const float*)d_in[19];
    float* out = (float*)d_out;

    float *xx, *ms0, *ms1, *rr, *kk, *vv, *gg, *ww, *y, *sc, *dpp;
    bf16 *wt5h, *wt5l, *w1th, *w1tl, *w2th, *w2tl, *dw1th, *dw1tl, *dw2th, *dw2tl;
    bf16 *xxxh, *xxxl, *mh, *ml, *xwh, *xwl, *xkh, *xkl, *xvh, *xvl;
    bf16 *xrh, *xrl, *xgh, *xgl, *t64h, *t64l, *zh, *zl;
    cudaGetSymbolAddress((void**)&xx,    g_xx);
    cudaGetSymbolAddress((void**)&ms0,   g_ms0);
    cudaGetSymbolAddress((void**)&ms1,   g_ms1);
    cudaGetSymbolAddress((void**)&rr,    g_r);
    cudaGetSymbolAddress((void**)&kk,    g_k);
    cudaGetSymbolAddress((void**)&vv,    g_v);
    cudaGetSymbolAddress((void**)&gg,    g_g);
    cudaGetSymbolAddress((void**)&ww,    g_w);
    cudaGetSymbolAddress((void**)&y,     g_y);
    cudaGetSymbolAddress((void**)&sc,    g_sc);
    cudaGetSymbolAddress((void**)&dpp,   g_dp);
    cudaGetSymbolAddress((void**)&wt5h,  g_wt5h);
    cudaGetSymbolAddress((void**)&wt5l,  g_wt5l);
    cudaGetSymbolAddress((void**)&w1th,  g_w1th);
    cudaGetSymbolAddress((void**)&w1tl,  g_w1tl);
    cudaGetSymbolAddress((void**)&w2th,  g_w2th);
    cudaGetSymbolAddress((void**)&w2tl,  g_w2tl);
    cudaGetSymbolAddress((void**)&dw1th, g_dw1th);
    cudaGetSymbolAddress((void**)&dw1tl, g_dw1tl);
    cudaGetSymbolAddress((void**)&dw2th, g_dw2th);
    cudaGetSymbolAddress((void**)&dw2tl, g_dw2tl);
    cudaGetSymbolAddress((void**)&xxxh,  g_xxxh);
    cudaGetSymbolAddress((void**)&xxxl,  g_xxxl);
    cudaGetSymbolAddress((void**)&mh,    g_mh);
    cudaGetSymbolAddress((void**)&ml,    g_ml);
    cudaGetSymbolAddress((void**)&xwh,   g_xwh);
    cudaGetSymbolAddress((void**)&xwl,   g_xwl);
    cudaGetSymbolAddress((void**)&xkh,   g_xkh);
    cudaGetSymbolAddress((void**)&xkl,   g_xkl);
    cudaGetSymbolAddress((void**)&xvh,   g_xvh);
    cudaGetSymbolAddress((void**)&xvl,   g_xvl);
    cudaGetSymbolAddress((void**)&xrh,   g_xrh);
    cudaGetSymbolAddress((void**)&xrl,   g_xrl);
    cudaGetSymbolAddress((void**)&xgh,   g_xgh);
    cudaGetSymbolAddress((void**)&xgl,   g_xgl);
    cudaGetSymbolAddress((void**)&t64h,  g_t64h);
    cudaGetSymbolAddress((void**)&t64l,  g_t64l);
    cudaGetSymbolAddress((void**)&zh,    g_zh);
    cudaGetSymbolAddress((void**)&zl,    g_zl);

    cudaFuncSetAttribute(gemm_bf16x3_kernel,
                         cudaFuncAttributeMaxDynamicSharedMemorySize, GSMEM_BYTES);

    const size_t WSZ = (size_t)Cc * Cc;
    dim3 tb(32, 8);

    // 0a) big weight transposes + split
    {
        TBatch j = {};
        const float* s5[5] = {W_r, W_k, W_v, W_g, W_o};
        for (int f = 0; f < 5; f++) {
            j.src[f] = s5[f];
            j.dsth[f] = wt5h + (size_t)f * WSZ;
            j.dstl[f] = wt5l + (size_t)f * WSZ;
            j.R[f] = 1024; j.C[f] = 1024;
        }
        for (int f = 5; f < 8; f++) {
            j.src[f] = W_r; j.dsth[f] = wt5h; j.dstl[f] = wt5l;
            j.R[f] = 0; j.C[f] = 0;
        }
        transpose_split_kernel<<<dim3(32, 32, 5), tb>>>(j);
    }
    // 0b) small transposes + split
    {
        TBatch j = {};
        j.src[0] = maa_w1; j.dsth[0] = w1th; j.dstl[0] = w1tl;
        j.R[0] = 1024; j.C[0] = 160;
        for (int f = 0; f < 5; f++) {
            j.src[1 + f]  = maa_w2 + (size_t)f * 32 * 1024;
            j.dsth[1 + f] = w2th + (size_t)f * 1024 * 32;
            j.dstl[1 + f] = w2tl + (size_t)f * 1024 * 32;
            j.R[1 + f] = 32; j.C[1 + f] = 1024;
        }
        j.src[6] = dw1; j.dsth[6] = dw1th; j.dstl[6] = dw1tl;
        j.R[6] = 1024; j.C[6] = 64;
        j.src[7] = dw2; j.dsth[7] = dw2th; j.dstl[7] = dw2tl;
        j.R[7] = 64; j.C[7] = 1024;
        transpose_split_kernel<<<dim3(32, 32, 8), tb>>>(j);
    }

    // 1) token shift (+ xxx split)
    shift_kernel<<<(MT * Cc + 255) / 256, 256>>>(x, maa_x, xx, xxxh, xxxl);

    // 2) m = tanh(xxx @ W1), split-K=2, combine writes bf16 pair
    {
        GemmBatch a = {};
        a.Ah[0] = xxxh;       a.Al[0] = xxxl;
        a.Bh[0] = w1th;       a.Bl[0] = w1tl;
        a.Ah[1] = xxxh + 512; a.Al[1] = xxxl + 512;
        a.Bh[1] = w1th + 512; a.Bl[1] = w1tl + 512;
        a.C[0] = ms0; a.C[1] = ms1;
        a.N[0] = a.N[1] = 160; a.ldc[0] = a.ldc[1] = 160;
        a.epi[0] = a.epi[1] = EPI_NONE; a.pair[0] = a.pair[1] = 0;
        a.K = 512; a.lda = 1024; a.ldb = 1024;
        gemm_bf16x3_kernel<<<dim3(2, 32, 2), 256, GSMEM_BYTES>>>(a);
        tanh_combine_kernel<<<(MT * 160 + 255) / 256, 256>>>(ms0, ms1, mh, ml, MT * 160);
    }

    // 3) five mixing GEMMs -> bf16 pair outputs
    {
        GemmBatch a = {};
        const float* bias5[5] = {maa_w, maa_k, maa_v, maa_r, maa_g};
        bf16* oh[5] = {xwh, xkh, xvh, xrh, xgh};
        bf16* ol[5] = {xwl, xkl, xvl, xrl, xgl};
        for (int f = 0; f < 5; f++) {
            a.Ah[f] = mh + f * 32; a.Al[f] = ml + f * 32;
            a.Bh[f] = w2th + (size_t)f * 1024 * 32;
            a.Bl[f] = w2tl + (size_t)f * 1024 * 32;
            a.Ch[f] = oh[f]; a.Cl[f] = ol[f];
            a.bias[f] = bias5[f];
            a.N[f] = 1024; a.ldc[f] = 1024; a.epi[f] = EPI_MIX; a.pair[f] = 1;
        }
        a.ex = x; a.exx = xx;
        a.K = 32; a.lda = 160; a.ldb = 32;
        gemm_bf16x3_kernel<<<dim3(8, 32, 5), 256, GSMEM_BYTES>>>(a);
    }

    // 4) projections r/k/v/g (f32 out) + decay LoRA-1 (bf16-pair out)
    {
        GemmBatch a = {};
        const bf16* Ahs[5] = {xrh, xkh, xvh, xgh, xwh};
        const bf16* Als[5] = {xrl, xkl, xvl, xgl, xwl};
        const bf16* Bhs[5] = {wt5h + 0 * WSZ, wt5h + 1 * WSZ, wt5h + 2 * WSZ,
                              wt5h + 3 * WSZ, dw1th};
        const bf16* Bls[5] = {wt5l + 0 * WSZ, wt5l + 1 * WSZ, wt5l + 2 * WSZ,
                              wt5l + 3 * WSZ, dw1tl};
        float* Cs[5] = {rr, kk, vv, gg, nullptr};
        int Ns[5]   = {1024, 1024, 1024, 1024, 64};
        int ldcs[5] = {1024, 1024, 1024, 1024, 64};
        int epis[5] = {EPI_NONE, EPI_NONE, EPI_NONE, EPI_SILU, EPI_TANH};
        int prs[5]  = {0, 0, 0, 0, 1};
        for (int f = 0; f < 5; f++) {
            a.Ah[f] = Ahs[f]; a.Al[f] = Als[f];
            a.Bh[f] = Bhs[f]; a.Bl[f] = Bls[f];
            a.C[f] = Cs[f];
            a.N[f] = Ns[f]; a.ldc[f] = ldcs[f]; a.epi[f] = epis[f]; a.pair[f] = prs[f];
        }
        a.Ch[4] = t64h; a.Cl[4] = t64l;
        a.K = 1024; a.lda = 1024; a.ldb = 1024;
        gemm_bf16x3_kernel<<<dim3(8, 32, 5), 256, GSMEM_BYTES>>>(a);
    }

    // 5) decay LoRA-2: w = time_decay + t64 @ dw2  (f32 out)
    {
        GemmBatch a = {};
        a.Ah[0] = t64h; a.Al[0] = t64l;
        a.Bh[0] = dw2th; a.Bl[0] = dw2tl;
        a.C[0] = ww; a.bias[0] = tdecay;
        a.N[0] = 1024; a.ldc[0] = 1024; a.epi[0] = EPI_BIAS; a.pair[0] = 0;
        a.K = 64; a.lda = 64; a.ldb = 64;
        gemm_bf16x3_kernel<<<dim3(8, 32, 1), 256, GSMEM_BYTES>>>(a);
    }

    // 6) chunked WKV6 scan
    wkv6_pass1_kernel<<<64 * NCHUNK, 64>>>(kk, vv, ww, sc, dpp);
    wkv6_pass2_kernel<<<64, 64>>>(sc, dpp);
    wkv6_pass3_kernel<<<64 * NCHUNK, 64>>>(rr, kk, vv, ww, u, sc, y);

    // 7) groupnorm + gate -> z bf16 pair
    gnorm_kernel<<<MT, 256>>>(y, gg, gamma, beta, zh, zl);

    // 8) output projection
    {
        GemmBatch a = {};
        a.Ah[0] = zh; a.Al[0] = zl;
        a.Bh[0] = wt5h + 4 * WSZ; a.Bl[0] = wt5l + 4 * WSZ;
        a.C[0] = out;
        a.N[0] = 1024; a.ldc[0] = 1024; a.epi[0] = EPI_NONE; a.pair[0] = 0;
        a.K = 1024; a.lda = 1024; a.ldb = 1024;
        gemm_bf16x3_kernel<<<dim3(8, 32, 1), 256, GSMEM_BYTES>>>(a);
    }
}